// round 13
// baseline (speedup 1.0000x reference)
#include <cuda_runtime.h>
#include <cuda_fp16.h>
#include <math.h>
#include <stdint.h>

// ---------------- problem constants ----------------
#define B_    2
#define S_    2048
#define H_    2048
#define NH_   16
#define QLORA 1536
#define KVLORA 512
#define DNOPE 128
#define DROPE 64
#define DV_   128
#define DQK   192
#define M_    (B_ * S_)    // 4096

// ---------------- fp32 scratch ----------------
__device__ __align__(16) float g_qa  [(size_t)M_ * QLORA];
__device__ __align__(16) float g_q   [(size_t)M_ * (NH_ * DQK)];
__device__ __align__(16) float g_kv  [(size_t)M_ * (KVLORA + DROPE)];
__device__ __align__(16) float g_kpe [(size_t)M_ * DROPE];
__device__ __align__(16) float g_kvx [(size_t)M_ * (NH_ * (DNOPE + DV_))];
__device__ float g_cos [S_ * (DROPE / 2)];
__device__ float g_sin [S_ * (DROPE / 2)];

// ---------------- fp16 operand buffers ----------------
__device__ __align__(16) __half g_hs_h [(size_t)M_ * H_];
__device__ __align__(16) __half g_wqa_h[(size_t)QLORA * H_];
__device__ __align__(16) __half g_wqb_h[(size_t)NH_ * DQK * QLORA];
__device__ __align__(16) __half g_wkva_h[(size_t)(KVLORA + DROPE) * H_];
__device__ __align__(16) __half g_wkvb_h[(size_t)NH_ * (DNOPE + DV_) * KVLORA];
__device__ __align__(16) __half g_wo_h [(size_t)H_ * NH_ * DV_];
__device__ __align__(16) __half g_qa_h [(size_t)M_ * QLORA];
__device__ __align__(16) __half g_qh   [(size_t)M_ * NH_ * DQK];
__device__ __align__(16) __half g_kvc_h[(size_t)M_ * KVLORA];
__device__ __align__(16) __half g_kf_h [(size_t)M_ * NH_ * DQK];
__device__ __align__(16) __half g_vt_h [(size_t)B_ * NH_ * DV_ * S_];
__device__ __align__(16) __half g_ao_h [(size_t)M_ * NH_ * DV_];

// ---------------- helpers ----------------
__device__ __forceinline__ uint32_t smem_u32(const void* p) {
    uint32_t a;
    asm("{ .reg .u64 t; cvta.to.shared.u64 t, %1; cvt.u32.u64 %0, t; }" : "=r"(a) : "l"(p));
    return a;
}

__device__ __forceinline__ void cp16(uint32_t dst, const void* src, bool pred) {
    int sz = pred ? 16 : 0;
    asm volatile("cp.async.cg.shared.global [%0], [%1], 16, %2;\n"
                 :: "r"(dst), "l"(src), "r"(sz));
}
#define CP_COMMIT()   asm volatile("cp.async.commit_group;\n" ::: "memory")
#define CP_WAIT(n)    asm volatile("cp.async.wait_group %0;\n" :: "n"(n) : "memory")

__device__ __forceinline__ void mma_fp16(float* c, const uint32_t* a, const uint32_t* b) {
    asm volatile(
        "mma.sync.aligned.m16n8k16.row.col.f32.f16.f16.f32 "
        "{%0,%1,%2,%3}, {%4,%5,%6,%7}, {%8,%9}, {%0,%1,%2,%3};\n"
        : "+f"(c[0]), "+f"(c[1]), "+f"(c[2]), "+f"(c[3])
        : "r"(a[0]), "r"(a[1]), "r"(a[2]), "r"(a[3]), "r"(b[0]), "r"(b[1]));
}

__device__ __forceinline__ void ldsm_x4(uint32_t* r, uint32_t addr) {
    asm volatile("ldmatrix.sync.aligned.m8n8.x4.shared.b16 {%0,%1,%2,%3}, [%4];"
        : "=r"(r[0]), "=r"(r[1]), "=r"(r[2]), "=r"(r[3]) : "r"(addr));
}

__device__ __forceinline__ uint32_t pack_h2(float a, float b) {
    __half2 h = __floats2half2_rn(a, b);
    return *(uint32_t*)&h;
}

// ---------------- pipelined fp16 tensor-core GEMM, tile 256x128 ----------------
// C[m,n] = alpha * sum_k A[m,k] * B[n,k]   (B row-major [n][k], K-contiguous)
// 512 threads (16 warps: 8 m-groups x 2 n-groups), K-chunk 32, 3-stage cp.async.
// smem/stage: A 256x80B = 20480, B 128x80B = 10240
#define STG_A   0
#define STG_B   20480
#define STG_BYTES 30720
#define GEMM_SMEM (3 * STG_BYTES)

extern __shared__ char sm_raw[];

__global__ void __launch_bounds__(512, 1)
hgemm(const __half* __restrict__ A,
      const __half* __restrict__ B,
      float* __restrict__ C,
      int N, int K, int lda, int ldb, int ldc, float alpha)
{
    const int tid = threadIdx.x;
    const int lane = tid & 31, w = tid >> 5;
    const int wm = (w >> 1) * 32, wn = (w & 1) * 64;
    const int m0 = blockIdx.y * 256, n0 = blockIdx.x * 128;
    const int fr = lane >> 2, fc = (lane & 3) * 2;
    const int nk = K >> 5;

    const uint32_t smem = smem_u32(sm_raw);

    uint32_t aoff[2], boff[4];
    {
        int r = wm + (lane & 15);
        int c = (lane >> 4) * 8;
        aoff[0] = (uint32_t)((r * 40 + c) * 2);
        aoff[1] = (uint32_t)(((r + 16) * 40 + c) * 2);
        int lnB = lane & 7;
        int pHi = lane >> 4;
        int kh  = ((lane >> 3) & 1) * 8;
#pragma unroll
        for (int p = 0; p < 4; p++) {
            int n = wn + (2 * p + pHi) * 8 + lnB;
            boff[p] = (uint32_t)((n * 40 + kh) * 2);
        }
    }

    // loader: 512 threads; A 256 rows (2 per thread), B 128 rows (1 per thread)
    const int lrow0 = tid >> 2, lch = tid & 3;
    const __half* gA  = A + (long long)(m0 + lrow0) * lda + lch * 8;
    const __half* gA2 = gA + 128ll * lda;
    const bool bp = (n0 + lrow0) < N;
    const __half* gB = B + (long long)(n0 + (bp ? lrow0 : 0)) * ldb + lch * 8;
    const uint32_t soA1 = (uint32_t)(lrow0 * 80 + lch * 16);
    const uint32_t soA2 = (uint32_t)((lrow0 + 128) * 80 + lch * 16);
    const uint32_t soB  = (uint32_t)(lrow0 * 80 + lch * 16);

    auto load_stage = [&](int kc, int st) {
        uint32_t sb = smem + st * STG_BYTES;
        cp16(sb + STG_A + soA1, gA  + kc, true);
        cp16(sb + STG_A + soA2, gA2 + kc, true);
        cp16(sb + STG_B + soB,  gB  + kc, bp);
        CP_COMMIT();
    };

    float acc[2][8][4] = {};

    load_stage(0, 0);
    if (nk > 1) load_stage(32, 1); else CP_COMMIT();

    for (int k = 0; k < nk; k++) {
        const int st = k % 3;
        if (k + 2 < nk) load_stage((k + 2) * 32, (k + 2) % 3);
        else CP_COMMIT();
        CP_WAIT(2);
        __syncthreads();

        const uint32_t sb = smem + st * STG_BYTES;

#pragma unroll
        for (int ks = 0; ks < 2; ks++) {
            const uint32_t kB = ks * 32;
            uint32_t a[2][4];
#pragma unroll
            for (int mt = 0; mt < 2; mt++)
                ldsm_x4(a[mt], sb + STG_A + aoff[mt] + kB);
#pragma unroll
            for (int p = 0; p < 4; p++) {
                uint32_t bh[4];
                ldsm_x4(bh, sb + STG_B + boff[p] + kB);
#pragma unroll
                for (int sub = 0; sub < 2; sub++) {
                    const int nt = 2 * p + sub;
#pragma unroll
                    for (int mt = 0; mt < 2; mt++)
                        mma_fp16(acc[mt][nt], a[mt], bh + 2 * sub);
                }
            }
        }
        __syncthreads();
    }

#pragma unroll
    for (int mt = 0; mt < 2; mt++) {
        int row = m0 + wm + mt * 16 + fr;
#pragma unroll
        for (int nt = 0; nt < 8; nt++) {
            int col = n0 + wn + nt * 8 + fc;
            if (col < N) {
                C[(long long)row * ldc + col]           = alpha * acc[mt][nt][0];
                C[(long long)row * ldc + col + 1]       = alpha * acc[mt][nt][1];
                C[(long long)(row + 8) * ldc + col]     = alpha * acc[mt][nt][2];
                C[(long long)(row + 8) * ldc + col + 1] = alpha * acc[mt][nt][3];
            }
        }
    }
}

// ---------------- fused flash attention (unchanged from R12) ----------------
#define FL_Q    0
#define FL_K    51200
#define FL_KS   25600
#define FL_V    102400
#define FL_P    120832
#define FL_RED  139264
#define FL_SMEM 141312

__global__ void __launch_bounds__(256, 1)
flash_attn(const __half* __restrict__ Qg,
           const __half* __restrict__ Kh,
           const __half* __restrict__ Vh,
           __half* __restrict__ Oh, float scale)
{
    const int z  = blockIdx.y;
    const int bb = z >> 4, hh = z & 15;
    const int q0 = blockIdx.x * 128;
    const int tid = threadIdx.x, lane = tid & 31, w = tid >> 5;
    const int wq = w >> 1, wk = w & 1;
    const int fr = lane >> 2, fc = (lane & 3) * 2;

    const uint32_t smem = smem_u32(sm_raw);

    const __half* Qb  = Qg + (long long)bb * S_ * (NH_ * DQK) + hh * DQK;
    const __half* Khb = Kh + (long long)bb * S_ * (NH_ * DQK) + hh * DQK;
    const __half* Vhb = Vh + (long long)z * DV_ * S_;

    auto load_Q = [&]() {
#pragma unroll
        for (int j = 0; j < 12; j++) {
            int idx = tid + 256 * j;
            int r = idx / 24, ch = idx % 24;
            cp16(smem + FL_Q + (uint32_t)(r * 200 + ch * 8) * 2,
                 Qb + (long long)(q0 + r) * (NH_ * DQK) + ch * 8, true);
        }
    };
    auto load_K = [&](int kb, int st) {
        uint32_t base = smem + FL_K + st * FL_KS;
#pragma unroll
        for (int j = 0; j < 6; j++) {
            int idx = tid + 256 * j;
            int r = idx / 24, ch = idx % 24;
            cp16(base + (uint32_t)(r * 200 + ch * 8) * 2,
                 Khb + (long long)(kb * 64 + r) * (NH_ * DQK) + ch * 8, true);
        }
    };
    auto load_V = [&](int kb) {
#pragma unroll
        for (int j = 0; j < 4; j++) {
            int idx = tid + 256 * j;
            int d = idx >> 3, ch = idx & 7;
            cp16(smem + FL_V + (uint32_t)(d * 72 + ch * 8) * 2,
                 Vhb + (long long)d * S_ + kb * 64 + ch * 8, true);
        }
    };

    uint32_t aQ[2], aP[2], bK[2], bV[4];
    {
        int r = wq * 32 + (lane & 15);
        int c = (lane >> 4) * 8;
        aQ[0] = (uint32_t)((r * 200 + c) * 2);
        aQ[1] = (uint32_t)(((r + 16) * 200 + c) * 2);
        aP[0] = (uint32_t)((r * 72 + c) * 2);
        aP[1] = (uint32_t)(((r + 16) * 72 + c) * 2);
        int lnB = lane & 7, pHi = lane >> 4, kh = ((lane >> 3) & 1) * 8;
#pragma unroll
        for (int p = 0; p < 2; p++) {
            int n = wk * 32 + (2 * p + pHi) * 8 + lnB;
            bK[p] = (uint32_t)((n * 200 + kh) * 2);
        }
#pragma unroll
        for (int p = 0; p < 4; p++) {
            int n = wk * 64 + (2 * p + pHi) * 8 + lnB;
            bV[p] = (uint32_t)((n * 72 + kh) * 2);
        }
    }

    float acc_o[2][8][4] = {};
    float m_st[4], l_st[4];
#pragma unroll
    for (int i = 0; i < 4; i++) { m_st[i] = -1e30f; l_st[i] = 0.f; }

    float* redm = (float*)(sm_raw + FL_RED);
    float* reds = (float*)(sm_raw + FL_RED + 1024);
    int rowi[4];
#pragma unroll
    for (int mt = 0; mt < 2; mt++)
#pragma unroll
        for (int rr = 0; rr < 2; rr++)
            rowi[mt * 2 + rr] = wq * 32 + mt * 16 + rr * 8 + fr;

    load_Q(); load_K(0, 0); CP_COMMIT();
    load_V(0);              CP_COMMIT();
    load_K(1, 1);           CP_COMMIT();

    for (int kb = 0; kb < 32; kb++) {
        if (kb == 31) { CP_WAIT(1); } else { CP_WAIT(2); }
        __syncthreads();

        float acc_s[2][4][4] = {};
        const uint32_t kbase = smem + FL_K + (kb & 1) * FL_KS;
#pragma unroll
        for (int ks = 0; ks < 12; ks++) {
            const uint32_t kB = ks * 32;
            uint32_t a[2][4];
            ldsm_x4(a[0], smem + FL_Q + aQ[0] + kB);
            ldsm_x4(a[1], smem + FL_Q + aQ[1] + kB);
#pragma unroll
            for (int p = 0; p < 2; p++) {
                uint32_t bh[4];
                ldsm_x4(bh, kbase + bK[p] + kB);
#pragma unroll
                for (int sub = 0; sub < 2; sub++) {
                    const int nt = 2 * p + sub;
#pragma unroll
                    for (int mt = 0; mt < 2; mt++)
                        mma_fp16(acc_s[mt][nt], a[mt], bh + 2 * sub);
                }
            }
        }
#pragma unroll
        for (int mt = 0; mt < 2; mt++)
#pragma unroll
            for (int nt = 0; nt < 4; nt++)
#pragma unroll
                for (int c = 0; c < 4; c++) acc_s[mt][nt][c] *= scale;

#pragma unroll
        for (int sl = 0; sl < 4; sl++) {
            int mt = sl >> 1, rr = sl & 1;
            float v = -1e30f;
#pragma unroll
            for (int nt = 0; nt < 4; nt++) {
                v = fmaxf(v, acc_s[mt][nt][2 * rr]);
                v = fmaxf(v, acc_s[mt][nt][2 * rr + 1]);
            }
            v = fmaxf(v, __shfl_xor_sync(0xffffffffu, v, 1));
            v = fmaxf(v, __shfl_xor_sync(0xffffffffu, v, 2));
            if ((lane & 3) == 0) redm[wk * 128 + rowi[sl]] = v;
        }
        __syncthreads();

        float alpha[4];
#pragma unroll
        for (int sl = 0; sl < 4; sl++) {
            float bm = fmaxf(redm[rowi[sl]], redm[128 + rowi[sl]]);
            float mn = fmaxf(m_st[sl], bm);
            alpha[sl] = __expf(m_st[sl] - mn);
            m_st[sl] = mn;
        }

#pragma unroll
        for (int sl = 0; sl < 4; sl++) {
            int mt = sl >> 1, rr = sl & 1;
            int prow = rowi[sl];
            float s = 0.f;
#pragma unroll
            for (int nt = 0; nt < 4; nt++) {
                float p0 = __expf(acc_s[mt][nt][2 * rr]     - m_st[sl]);
                float p1 = __expf(acc_s[mt][nt][2 * rr + 1] - m_st[sl]);
                s += p0 + p1;
                *(__half2*)(sm_raw + FL_P + (prow * 72 + wk * 32 + nt * 8 + fc) * 2)
                    = __floats2half2_rn(p0, p1);
            }
            s += __shfl_xor_sync(0xffffffffu, s, 1);
            s += __shfl_xor_sync(0xffffffffu, s, 2);
            if ((lane & 3) == 0) reds[wk * 128 + prow] = s;
        }

        if (kb == 31) { CP_WAIT(0); } else { CP_WAIT(1); }
        __syncthreads();

#pragma unroll
        for (int sl = 0; sl < 4; sl++)
            l_st[sl] = alpha[sl] * l_st[sl] + reds[rowi[sl]] + reds[128 + rowi[sl]];

#pragma unroll
        for (int mt = 0; mt < 2; mt++)
#pragma unroll
            for (int nt = 0; nt < 8; nt++)
#pragma unroll
                for (int rr = 0; rr < 2; rr++) {
                    float a = alpha[mt * 2 + rr];
                    acc_o[mt][nt][2 * rr]     *= a;
                    acc_o[mt][nt][2 * rr + 1] *= a;
                }

#pragma unroll
        for (int ks = 0; ks < 4; ks++) {
            const uint32_t kB = ks * 32;
            uint32_t a[2][4];
            ldsm_x4(a[0], smem + FL_P + aP[0] + kB);
            ldsm_x4(a[1], smem + FL_P + aP[1] + kB);
#pragma unroll
            for (int p = 0; p < 4; p++) {
                uint32_t bh[4];
                ldsm_x4(bh, smem + FL_V + bV[p] + kB);
#pragma unroll
                for (int sub = 0; sub < 2; sub++) {
                    const int nt = 2 * p + sub;
#pragma unroll
                    for (int mt = 0; mt < 2; mt++)
                        mma_fp16(acc_o[mt][nt], a[mt], bh + 2 * sub);
                }
            }
        }
        __syncthreads();

        if (kb + 1 < 32) { load_V(kb + 1);         CP_COMMIT(); }
        if (kb + 2 < 32) { load_K(kb + 2, kb & 1); CP_COMMIT(); }
    }

    __half* Ob = Oh + (long long)bb * S_ * (NH_ * DV_) + hh * DV_;
#pragma unroll
    for (int mt = 0; mt < 2; mt++)
#pragma unroll
        for (int rr = 0; rr < 2; rr++) {
            int sl = mt * 2 + rr;
            float inv = 1.f / l_st[sl];
            long long row = q0 + rowi[sl];
#pragma unroll
            for (int nt = 0; nt < 8; nt++) {
                int col = wk * 64 + nt * 8 + fc;
                *(__half2*)(Ob + row * (NH_ * DV_) + col) =
                    __floats2half2_rn(acc_o[mt][nt][2 * rr] * inv,
                                      acc_o[mt][nt][2 * rr + 1] * inv);
            }
        }
}

// ---------------- fp32 -> fp16, vectorized 8 elems/thread ----------------
__global__ void convert_h_kernel(const float* __restrict__ x,
                                 __half* __restrict__ h, long long n)
{
    long long i = ((long long)blockIdx.x * 256 + threadIdx.x) * 8;
    if (i < n) {
        float4 a = *(const float4*)(x + i);
        float4 b = *(const float4*)(x + i + 4);
        uint4 o;
        o.x = pack_h2(a.x, a.y);
        o.y = pack_h2(a.z, a.w);
        o.z = pack_h2(b.x, b.y);
        o.w = pack_h2(b.z, b.w);
        *(uint4*)(h + i) = o;
    }
}

// ---------------- RMSNorm -> fp16, vectorized ----------------
__global__ void __launch_bounds__(256)
rmsnorm_h_kernel(const float* __restrict__ x, int ldx, const float* __restrict__ w,
                 __half* __restrict__ yh, int ldy, int cols)
{
    const int row = blockIdx.x;
    const float* xr = x + (long long)row * ldx;
    float ss = 0.f;
    for (int c = threadIdx.x * 4; c < cols; c += 1024) {
        float4 v = *(const float4*)(xr + c);
        ss += v.x * v.x + v.y * v.y + v.z * v.z + v.w * v.w;
    }
    __shared__ float red[256];
    red[threadIdx.x] = ss;
    __syncthreads();
    for (int s = 128; s > 0; s >>= 1) {
        if (threadIdx.x < s) red[threadIdx.x] += red[threadIdx.x + s];
        __syncthreads();
    }
    float inv = 1.f / sqrtf(red[0] / (float)cols + 1e-6f);
    long long base = (long long)row * ldy;
    for (int c = threadIdx.x * 4; c < cols; c += 1024) {
        float4 v = *(const float4*)(xr + c);
        float4 wv = *(const float4*)(w + c);
        uint2 o;
        o.x = pack_h2(wv.x * v.x * inv, wv.y * v.y * inv);
        o.y = pack_h2(wv.z * v.z * inv, wv.w * v.w * inv);
        *(uint2*)(yh + base + c) = o;
    }
}

// ---------------- RoPE ----------------
__global__ void freqs_kernel(float* __restrict__ cosd, float* __restrict__ sind)
{
    int t = blockIdx.x, i = threadIdx.x;
    double inv = pow(10000.0, -(double)(2 * i) / (double)DROPE);
    double f = (double)t * inv;
    cosd[t * 32 + i] = (float)cos(f);
    sind[t * 32 + i] = (float)sin(f);
}

// fused: rope on q_pe dims + fp16 convert of full q row -> q_h (8 floats/thread)
__global__ void __launch_bounds__(256)
rope_q_convert_kernel(const float* __restrict__ q, __half* __restrict__ qh,
                      const float* __restrict__ cosd, const float* __restrict__ sind)
{
    int m = blockIdx.x;
    int t = m & (S_ - 1);
    long long base = (long long)m * (NH_ * DQK);
    const float* ct = cosd + t * 32;
    const float* st = sind + t * 32;
#pragma unroll
    for (int j = 0; j < 2; j++) {
        int g = threadIdx.x + 256 * j;           // group of 8 floats; 384 groups
        if (g >= 384) break;
        int col = g * 8;
        int d = col % DQK;
        float4 a = *(const float4*)(q + base + col);
        float4 b = *(const float4*)(q + base + col + 4);
        if (d >= DNOPE) {
            int i0 = (d - DNOPE) >> 1;
            float v[8] = {a.x, a.y, a.z, a.w, b.x, b.y, b.z, b.w};
#pragma unroll
            for (int p = 0; p < 4; p++) {
                float cs = ct[i0 + p], sn = st[i0 + p];
                float e = v[2 * p], o = v[2 * p + 1];
                v[2 * p]     = e * cs - o * sn;
                v[2 * p + 1] = e * sn + o * cs;
            }
            a = make_float4(v[0], v[1], v[2], v[3]);
            b = make_float4(v[4], v[5], v[6], v[7]);
        }
        uint4 o;
        o.x = pack_h2(a.x, a.y);
        o.y = pack_h2(a.z, a.w);
        o.z = pack_h2(b.x, b.y);
        o.w = pack_h2(b.z, b.w);
        *(uint4*)(qh + base + col) = o;
    }
}

__global__ void rope_k_kernel(const float* __restrict__ kv, float* __restrict__ kpe,
                              const float* __restrict__ cosd, const float* __restrict__ sind)
{
    int m = blockIdx.x;
    int t = m & (S_ - 1);
    int i = threadIdx.x;
    float cs = cosd[t * 32 + i], sn = sind[t * 32 + i];
    long long base = (long long)m * (KVLORA + DROPE) + KVLORA + 2 * i;
    float e = kv[base], o = kv[base + 1];
    kpe[m * DROPE + 2 * i]     = e * cs - o * sn;
    kpe[m * DROPE + 2 * i + 1] = e * sn + o * cs;
}

// ---------------- kf assembly (fp16), 8 elems/thread ----------------
__global__ void build_kf_kernel(const float* __restrict__ kvx, const float* __restrict__ kpe,
                                __half* __restrict__ kfh)
{
    long long idx = (long long)blockIdx.x * 256 + threadIdx.x;  // group id < M_*384
    int g = (int)(idx % 384);
    long long m = idx / 384;
    int col = g * 8;
    int h = col / DQK, d = col % DQK;
    const float* src = (d < DNOPE)
        ? kvx + m * (NH_ * (DNOPE + DV_)) + h * (DNOPE + DV_) + d
        : kpe + m * DROPE + (d - DNOPE);
    float4 a = *(const float4*)(src);
    float4 b = *(const float4*)(src + 4);
    uint4 o;
    o.x = pack_h2(a.x, a.y);
    o.y = pack_h2(a.z, a.w);
    o.z = pack_h2(b.x, b.y);
    o.w = pack_h2(b.z, b.w);
    *(uint4*)(kfh + (long long)m * (NH_ * DQK) + col) = o;
}

// ---------------- V extraction + transpose: vt[b][h][d][s] ----------------
__global__ void __launch_bounds__(256)
transpose_v_kernel(const float* __restrict__ kvx, __half* __restrict__ vth)
{
    __shared__ float t[32][33];
    int z = blockIdx.z;
    int b = z / NH_, h = z % NH_;
    int s0 = blockIdx.x * 32, d0 = blockIdx.y * 32;
    int tx = threadIdx.x & 31, ty = threadIdx.x >> 5;
#pragma unroll
    for (int i = ty; i < 32; i += 8)
        t[i][tx] = kvx[((long long)(b * S_ + s0 + i)) * (NH_ * (DNOPE + DV_))
                       + h * (DNOPE + DV_) + DNOPE + d0 + tx];
    __syncthreads();
#pragma unroll
    for (int i = ty; i < 32; i += 8) {
        long long o = ((long long)z * DV_ + d0 + i) * S_ + s0 + tx;
        vth[o] = __float2half_rn(t[tx][i]);
    }
}

// ---------------- launch ----------------
extern "C" void kernel_launch(void* const* d_in, const int* in_sizes, int n_in,
                              void* d_out, int out_size)
{
    const float* hs        = (const float*)d_in[0];
    const float* wq_a      = (const float*)d_in[1];
    const float* q_norm_w  = (const float*)d_in[2];
    const float* wq_b      = (const float*)d_in[3];
    const float* wkv_a     = (const float*)d_in[4];
    const float* kv_norm_w = (const float*)d_in[5];
    const float* wkv_b     = (const float*)d_in[6];
    const float* wo        = (const float*)d_in[7];
    float* out = (float*)d_out;

    cudaFuncSetAttribute(hgemm, cudaFuncAttributeMaxDynamicSharedMemorySize, GEMM_SMEM);
    cudaFuncSetAttribute(flash_attn, cudaFuncAttributeMaxDynamicSharedMemorySize, FL_SMEM);

    float *p_qa, *p_q, *p_kv, *p_kpe, *p_kvx, *p_cos, *p_sin;
    cudaGetSymbolAddress((void**)&p_qa,  g_qa);
    cudaGetSymbolAddress((void**)&p_q,   g_q);
    cudaGetSymbolAddress((void**)&p_kv,  g_kv);
    cudaGetSymbolAddress((void**)&p_kpe, g_kpe);
    cudaGetSymbolAddress((void**)&p_kvx, g_kvx);
    cudaGetSymbolAddress((void**)&p_cos, g_cos);
    cudaGetSymbolAddress((void**)&p_sin, g_sin);

    __half *hs_h, *wqa_h, *wqb_h, *wkva_h, *wkvb_h, *wo_h, *qa_h, *q_h;
    __half *kvc_h, *kf_h, *vt_h, *ao_h;
    cudaGetSymbolAddress((void**)&hs_h,  g_hs_h);
    cudaGetSymbolAddress((void**)&wqa_h, g_wqa_h);
    cudaGetSymbolAddress((void**)&wqb_h, g_wqb_h);
    cudaGetSymbolAddress((void**)&wkva_h, g_wkva_h);
    cudaGetSymbolAddress((void**)&wkvb_h, g_wkvb_h);
    cudaGetSymbolAddress((void**)&wo_h,  g_wo_h);
    cudaGetSymbolAddress((void**)&qa_h,  g_qa_h);
    cudaGetSymbolAddress((void**)&q_h,   g_qh);
    cudaGetSymbolAddress((void**)&kvc_h, g_kvc_h);
    cudaGetSymbolAddress((void**)&kf_h,  g_kf_h);
    cudaGetSymbolAddress((void**)&vt_h,  g_vt_h);
    cudaGetSymbolAddress((void**)&ao_h,  g_ao_h);

    const float scale = 1.0f / sqrtf((float)DQK);
    auto cv8 = [](long long n) { return (int)((n / 8 + 255) / 256); };
    auto ntiles = [](int n) { return (n + 127) / 128; };

    freqs_kernel<<<S_, 32>>>(p_cos, p_sin);

    convert_h_kernel<<<cv8((long long)M_ * H_), 256>>>(hs, hs_h, (long long)M_ * H_);
    convert_h_kernel<<<cv8((long long)QLORA * H_), 256>>>(wq_a, wqa_h, (long long)QLORA * H_);
    convert_h_kernel<<<cv8((long long)NH_ * DQK * QLORA), 256>>>(wq_b, wqb_h, (long long)NH_ * DQK * QLORA);
    convert_h_kernel<<<cv8((long long)(KVLORA + DROPE) * H_), 256>>>(wkv_a, wkva_h, (long long)(KVLORA + DROPE) * H_);
    convert_h_kernel<<<cv8((long long)NH_ * (DNOPE + DV_) * KVLORA), 256>>>(wkv_b, wkvb_h, (long long)NH_ * (DNOPE + DV_) * KVLORA);
    convert_h_kernel<<<cv8((long long)H_ * NH_ * DV_), 256>>>(wo, wo_h, (long long)H_ * NH_ * DV_);

    // q_a = hs @ wq_a^T   [4096 x 1536] K=2048
    hgemm<<<dim3(ntiles(QLORA), M_ / 256, 1), 512, GEMM_SMEM>>>(
        hs_h, wqa_h, p_qa, QLORA, H_, H_, H_, QLORA, 1.f);

    rmsnorm_h_kernel<<<M_, 256>>>(p_qa, QLORA, q_norm_w, qa_h, QLORA, QLORA);

    // q = q_a @ wq_b^T    [4096 x 3072] K=1536
    hgemm<<<dim3(ntiles(NH_ * DQK), M_ / 256, 1), 512, GEMM_SMEM>>>(
        qa_h, wqb_h, p_q, NH_ * DQK, QLORA, QLORA, QLORA, NH_ * DQK, 1.f);

    // kv = hs @ wkv_a^T   [4096 x 576] K=2048
    hgemm<<<dim3(ntiles(KVLORA + DROPE), M_ / 256, 1), 512, GEMM_SMEM>>>(
        hs_h, wkva_h, p_kv, KVLORA + DROPE, H_, H_, H_, KVLORA + DROPE, 1.f);

    rmsnorm_h_kernel<<<M_, 256>>>(p_kv, KVLORA + DROPE, kv_norm_w, kvc_h, KVLORA, KVLORA);
    rope_k_kernel<<<M_, 32>>>(p_kv, p_kpe, p_cos, p_sin);

    // kv_x = kv_c @ wkv_b^T  [4096 x 4096] K=512
    hgemm<<<dim3(ntiles(NH_ * (DNOPE + DV_)), M_ / 256, 1), 512, GEMM_SMEM>>>(
        kvc_h, wkvb_h, p_kvx, NH_ * (DNOPE + DV_), KVLORA, KVLORA, KVLORA,
        NH_ * (DNOPE + DV_), 1.f);

    rope_q_convert_kernel<<<M_, 256>>>(p_q, q_h, p_cos, p_sin);
    build_kf_kernel<<<(int)(((long long)M_ * 384 + 255) / 256), 256>>>(p_kvx, p_kpe, kf_h);
    transpose_v_kernel<<<dim3(S_ / 32, DV_ / 32, B_ * NH_), 256>>>(p_kvx, vt_h);

    // fused attention: ao_h = softmax(scale * Q Kf^T) V
    flash_attn<<<dim3(S_ / 128, B_ * NH_), 256, FL_SMEM>>>(
        q_h, kf_h, vt_h, ao_h, scale);

    // out = ao @ wo^T   [4096 x 2048] K=2048
    hgemm<<<dim3(ntiles(H_), M_ / 256, 1), 512, GEMM_SMEM>>>(
        ao_h, wo_h, out, H_, NH_ * DV_, NH_ * DV_, NH_ * DV_, H_, 1.f);
}

// round 14
// speedup vs baseline: 1.1006x; 1.1006x over previous
#include <cuda_runtime.h>
#include <cuda_fp16.h>
#include <math.h>
#include <stdint.h>

// ---------------- problem constants ----------------
#define B_    2
#define S_    2048
#define H_    2048
#define NH_   16
#define QLORA 1536
#define KVLORA 512
#define DNOPE 128
#define DROPE 64
#define DV_   128
#define DQK   192
#define M_    (B_ * S_)    // 4096

// ---------------- fp32 scratch ----------------
__device__ __align__(16) float g_qa  [(size_t)M_ * QLORA];
__device__ __align__(16) float g_q   [(size_t)M_ * (NH_ * DQK)];
__device__ __align__(16) float g_kv  [(size_t)M_ * (KVLORA + DROPE)];
__device__ __align__(16) float g_kpe [(size_t)M_ * DROPE];
__device__ __align__(16) float g_kvx [(size_t)M_ * (NH_ * (DNOPE + DV_))];
__device__ float g_cos [S_ * (DROPE / 2)];
__device__ float g_sin [S_ * (DROPE / 2)];

// ---------------- fp16 operand buffers ----------------
__device__ __align__(16) __half g_hs_h [(size_t)M_ * H_];
__device__ __align__(16) __half g_wqa_h[(size_t)QLORA * H_];
__device__ __align__(16) __half g_wqb_h[(size_t)NH_ * DQK * QLORA];
__device__ __align__(16) __half g_wkva_h[(size_t)(KVLORA + DROPE) * H_];
__device__ __align__(16) __half g_wkvb_h[(size_t)NH_ * (DNOPE + DV_) * KVLORA];
__device__ __align__(16) __half g_wo_h [(size_t)H_ * NH_ * DV_];
__device__ __align__(16) __half g_qa_h [(size_t)M_ * QLORA];
__device__ __align__(16) __half g_qh   [(size_t)M_ * NH_ * DQK];
__device__ __align__(16) __half g_kvc_h[(size_t)M_ * KVLORA];
__device__ __align__(16) __half g_kf_h [(size_t)M_ * NH_ * DQK];
__device__ __align__(16) __half g_vt_h [(size_t)B_ * NH_ * DV_ * S_];
__device__ __align__(16) __half g_ao_h [(size_t)M_ * NH_ * DV_];

// ---------------- helpers ----------------
__device__ __forceinline__ uint32_t smem_u32(const void* p) {
    uint32_t a;
    asm("{ .reg .u64 t; cvta.to.shared.u64 t, %1; cvt.u32.u64 %0, t; }" : "=r"(a) : "l"(p));
    return a;
}

__device__ __forceinline__ void cp16(uint32_t dst, const void* src, bool pred) {
    int sz = pred ? 16 : 0;
    asm volatile("cp.async.cg.shared.global [%0], [%1], 16, %2;\n"
                 :: "r"(dst), "l"(src), "r"(sz));
}
#define CP_COMMIT()   asm volatile("cp.async.commit_group;\n" ::: "memory")
#define CP_WAIT(n)    asm volatile("cp.async.wait_group %0;\n" :: "n"(n) : "memory")

__device__ __forceinline__ void mma_fp16(float* c, const uint32_t* a, const uint32_t* b) {
    asm volatile(
        "mma.sync.aligned.m16n8k16.row.col.f32.f16.f16.f32 "
        "{%0,%1,%2,%3}, {%4,%5,%6,%7}, {%8,%9}, {%0,%1,%2,%3};\n"
        : "+f"(c[0]), "+f"(c[1]), "+f"(c[2]), "+f"(c[3])
        : "r"(a[0]), "r"(a[1]), "r"(a[2]), "r"(a[3]), "r"(b[0]), "r"(b[1]));
}

__device__ __forceinline__ void ldsm_x4(uint32_t* r, uint32_t addr) {
    asm volatile("ldmatrix.sync.aligned.m8n8.x4.shared.b16 {%0,%1,%2,%3}, [%4];"
        : "=r"(r[0]), "=r"(r[1]), "=r"(r[2]), "=r"(r[3]) : "r"(addr));
}

__device__ __forceinline__ uint32_t pack_h2(float a, float b) {
    __half2 h = __floats2half2_rn(a, b);
    return *(uint32_t*)&h;
}

// ---------------- pipelined fp16 tensor-core GEMM, tile 128x128 (R12 shape) ----------------
// C[m,n] = alpha * sum_k A[m,k] * B[n,k]   (B row-major [n][k], K-contiguous)
// 256 threads, K-chunk 32, 3-stage cp.async, 2 CTA/SM.
#define STG_A   0
#define STG_B   10240
#define STG_BYTES 20480
#define GEMM_SMEM (3 * STG_BYTES)

extern __shared__ char sm_raw[];

__global__ void __launch_bounds__(256, 2)
hgemm(const __half* __restrict__ A,
      const __half* __restrict__ B,
      float* __restrict__ C,
      int N, int K, int lda, int ldb, int ldc, float alpha)
{
    const int tid = threadIdx.x;
    const int lane = tid & 31, w = tid >> 5;
    const int wm = (w >> 1) * 32, wn = (w & 1) * 64;
    const int m0 = blockIdx.y * 128, n0 = blockIdx.x * 128;
    const int fr = lane >> 2, fc = (lane & 3) * 2;
    const int nk = K >> 5;

    const uint32_t smem = smem_u32(sm_raw);

    uint32_t aoff[2], boff[4];
    {
        int r = wm + (lane & 15);
        int c = (lane >> 4) * 8;
        aoff[0] = (uint32_t)((r * 40 + c) * 2);
        aoff[1] = (uint32_t)(((r + 16) * 40 + c) * 2);
        int lnB = lane & 7;
        int pHi = lane >> 4;
        int kh  = ((lane >> 3) & 1) * 8;
#pragma unroll
        for (int p = 0; p < 4; p++) {
            int n = wn + (2 * p + pHi) * 8 + lnB;
            boff[p] = (uint32_t)((n * 40 + kh) * 2);
        }
    }

    const int lrow0 = tid >> 2, lch = tid & 3;
    const __half* gA  = A + (long long)(m0 + lrow0) * lda + lch * 8;
    const __half* gA2 = gA + 64ll * lda;
    const bool bp1 = (n0 + lrow0) < N;
    const bool bp2 = (n0 + lrow0 + 64) < N;
    const __half* gB  = B + (long long)(n0 + (bp1 ? lrow0 : 0)) * ldb + lch * 8;
    const __half* gB2 = B + (long long)(n0 + (bp2 ? lrow0 + 64 : 0)) * ldb + lch * 8;
    const uint32_t so1 = (uint32_t)(lrow0 * 80 + lch * 16);
    const uint32_t so2 = (uint32_t)((lrow0 + 64) * 80 + lch * 16);

    auto load_stage = [&](int kc, int st) {
        uint32_t sb = smem + st * STG_BYTES;
        cp16(sb + STG_A + so1, gA  + kc, true);
        cp16(sb + STG_A + so2, gA2 + kc, true);
        cp16(sb + STG_B + so1, gB  + kc, bp1);
        cp16(sb + STG_B + so2, gB2 + kc, bp2);
        CP_COMMIT();
    };

    float acc[2][8][4] = {};

    load_stage(0, 0);
    if (nk > 1) load_stage(32, 1); else CP_COMMIT();

    for (int k = 0; k < nk; k++) {
        const int st = k % 3;
        if (k + 2 < nk) load_stage((k + 2) * 32, (k + 2) % 3);
        else CP_COMMIT();
        CP_WAIT(2);
        __syncthreads();

        const uint32_t sb = smem + st * STG_BYTES;

#pragma unroll
        for (int ks = 0; ks < 2; ks++) {
            const uint32_t kB = ks * 32;
            uint32_t a[2][4];
#pragma unroll
            for (int mt = 0; mt < 2; mt++)
                ldsm_x4(a[mt], sb + STG_A + aoff[mt] + kB);
#pragma unroll
            for (int p = 0; p < 4; p++) {
                uint32_t bh[4];
                ldsm_x4(bh, sb + STG_B + boff[p] + kB);
#pragma unroll
                for (int sub = 0; sub < 2; sub++) {
                    const int nt = 2 * p + sub;
#pragma unroll
                    for (int mt = 0; mt < 2; mt++)
                        mma_fp16(acc[mt][nt], a[mt], bh + 2 * sub);
                }
            }
        }
        __syncthreads();
    }

#pragma unroll
    for (int mt = 0; mt < 2; mt++) {
        int row = m0 + wm + mt * 16 + fr;
#pragma unroll
        for (int nt = 0; nt < 8; nt++) {
            int col = n0 + wn + nt * 8 + fc;
            if (col < N) {
                C[(long long)row * ldc + col]           = alpha * acc[mt][nt][0];
                C[(long long)row * ldc + col + 1]       = alpha * acc[mt][nt][1];
                C[(long long)(row + 8) * ldc + col]     = alpha * acc[mt][nt][2];
                C[(long long)(row + 8) * ldc + col + 1] = alpha * acc[mt][nt][3];
            }
        }
    }
}

// ---------------- fused flash attention (R12, unchanged) ----------------
#define FL_Q    0
#define FL_K    51200
#define FL_KS   25600
#define FL_V    102400
#define FL_P    120832
#define FL_RED  139264
#define FL_SMEM 141312

__global__ void __launch_bounds__(256, 1)
flash_attn(const __half* __restrict__ Qg,
           const __half* __restrict__ Kh,
           const __half* __restrict__ Vh,
           __half* __restrict__ Oh, float scale)
{
    const int z  = blockIdx.y;
    const int bb = z >> 4, hh = z & 15;
    const int q0 = blockIdx.x * 128;
    const int tid = threadIdx.x, lane = tid & 31, w = tid >> 5;
    const int wq = w >> 1, wk = w & 1;
    const int fr = lane >> 2, fc = (lane & 3) * 2;

    const uint32_t smem = smem_u32(sm_raw);

    const __half* Qb  = Qg + (long long)bb * S_ * (NH_ * DQK) + hh * DQK;
    const __half* Khb = Kh + (long long)bb * S_ * (NH_ * DQK) + hh * DQK;
    const __half* Vhb = Vh + (long long)z * DV_ * S_;

    auto load_Q = [&]() {
#pragma unroll
        for (int j = 0; j < 12; j++) {
            int idx = tid + 256 * j;
            int r = idx / 24, ch = idx % 24;
            cp16(smem + FL_Q + (uint32_t)(r * 200 + ch * 8) * 2,
                 Qb + (long long)(q0 + r) * (NH_ * DQK) + ch * 8, true);
        }
    };
    auto load_K = [&](int kb, int st) {
        uint32_t base = smem + FL_K + st * FL_KS;
#pragma unroll
        for (int j = 0; j < 6; j++) {
            int idx = tid + 256 * j;
            int r = idx / 24, ch = idx % 24;
            cp16(base + (uint32_t)(r * 200 + ch * 8) * 2,
                 Khb + (long long)(kb * 64 + r) * (NH_ * DQK) + ch * 8, true);
        }
    };
    auto load_V = [&](int kb) {
#pragma unroll
        for (int j = 0; j < 4; j++) {
            int idx = tid + 256 * j;
            int d = idx >> 3, ch = idx & 7;
            cp16(smem + FL_V + (uint32_t)(d * 72 + ch * 8) * 2,
                 Vhb + (long long)d * S_ + kb * 64 + ch * 8, true);
        }
    };

    uint32_t aQ[2], aP[2], bK[2], bV[4];
    {
        int r = wq * 32 + (lane & 15);
        int c = (lane >> 4) * 8;
        aQ[0] = (uint32_t)((r * 200 + c) * 2);
        aQ[1] = (uint32_t)(((r + 16) * 200 + c) * 2);
        aP[0] = (uint32_t)((r * 72 + c) * 2);
        aP[1] = (uint32_t)(((r + 16) * 72 + c) * 2);
        int lnB = lane & 7, pHi = lane >> 4, kh = ((lane >> 3) & 1) * 8;
#pragma unroll
        for (int p = 0; p < 2; p++) {
            int n = wk * 32 + (2 * p + pHi) * 8 + lnB;
            bK[p] = (uint32_t)((n * 200 + kh) * 2);
        }
#pragma unroll
        for (int p = 0; p < 4; p++) {
            int n = wk * 64 + (2 * p + pHi) * 8 + lnB;
            bV[p] = (uint32_t)((n * 72 + kh) * 2);
        }
    }

    float acc_o[2][8][4] = {};
    float m_st[4], l_st[4];
#pragma unroll
    for (int i = 0; i < 4; i++) { m_st[i] = -1e30f; l_st[i] = 0.f; }

    float* redm = (float*)(sm_raw + FL_RED);
    float* reds = (float*)(sm_raw + FL_RED + 1024);
    int rowi[4];
#pragma unroll
    for (int mt = 0; mt < 2; mt++)
#pragma unroll
        for (int rr = 0; rr < 2; rr++)
            rowi[mt * 2 + rr] = wq * 32 + mt * 16 + rr * 8 + fr;

    load_Q(); load_K(0, 0); CP_COMMIT();
    load_V(0);              CP_COMMIT();
    load_K(1, 1);           CP_COMMIT();

    for (int kb = 0; kb < 32; kb++) {
        if (kb == 31) { CP_WAIT(1); } else { CP_WAIT(2); }
        __syncthreads();

        float acc_s[2][4][4] = {};
        const uint32_t kbase = smem + FL_K + (kb & 1) * FL_KS;
#pragma unroll
        for (int ks = 0; ks < 12; ks++) {
            const uint32_t kB = ks * 32;
            uint32_t a[2][4];
            ldsm_x4(a[0], smem + FL_Q + aQ[0] + kB);
            ldsm_x4(a[1], smem + FL_Q + aQ[1] + kB);
#pragma unroll
            for (int p = 0; p < 2; p++) {
                uint32_t bh[4];
                ldsm_x4(bh, kbase + bK[p] + kB);
#pragma unroll
                for (int sub = 0; sub < 2; sub++) {
                    const int nt = 2 * p + sub;
#pragma unroll
                    for (int mt = 0; mt < 2; mt++)
                        mma_fp16(acc_s[mt][nt], a[mt], bh + 2 * sub);
                }
            }
        }
#pragma unroll
        for (int mt = 0; mt < 2; mt++)
#pragma unroll
            for (int nt = 0; nt < 4; nt++)
#pragma unroll
                for (int c = 0; c < 4; c++) acc_s[mt][nt][c] *= scale;

#pragma unroll
        for (int sl = 0; sl < 4; sl++) {
            int mt = sl >> 1, rr = sl & 1;
            float v = -1e30f;
#pragma unroll
            for (int nt = 0; nt < 4; nt++) {
                v = fmaxf(v, acc_s[mt][nt][2 * rr]);
                v = fmaxf(v, acc_s[mt][nt][2 * rr + 1]);
            }
            v = fmaxf(v, __shfl_xor_sync(0xffffffffu, v, 1));
            v = fmaxf(v, __shfl_xor_sync(0xffffffffu, v, 2));
            if ((lane & 3) == 0) redm[wk * 128 + rowi[sl]] = v;
        }
        __syncthreads();

        float alpha[4];
#pragma unroll
        for (int sl = 0; sl < 4; sl++) {
            float bm = fmaxf(redm[rowi[sl]], redm[128 + rowi[sl]]);
            float mn = fmaxf(m_st[sl], bm);
            alpha[sl] = __expf(m_st[sl] - mn);
            m_st[sl] = mn;
        }

#pragma unroll
        for (int sl = 0; sl < 4; sl++) {
            int mt = sl >> 1, rr = sl & 1;
            int prow = rowi[sl];
            float s = 0.f;
#pragma unroll
            for (int nt = 0; nt < 4; nt++) {
                float p0 = __expf(acc_s[mt][nt][2 * rr]     - m_st[sl]);
                float p1 = __expf(acc_s[mt][nt][2 * rr + 1] - m_st[sl]);
                s += p0 + p1;
                *(__half2*)(sm_raw + FL_P + (prow * 72 + wk * 32 + nt * 8 + fc) * 2)
                    = __floats2half2_rn(p0, p1);
            }
            s += __shfl_xor_sync(0xffffffffu, s, 1);
            s += __shfl_xor_sync(0xffffffffu, s, 2);
            if ((lane & 3) == 0) reds[wk * 128 + prow] = s;
        }

        if (kb == 31) { CP_WAIT(0); } else { CP_WAIT(1); }
        __syncthreads();

#pragma unroll
        for (int sl = 0; sl < 4; sl++)
            l_st[sl] = alpha[sl] * l_st[sl] + reds[rowi[sl]] + reds[128 + rowi[sl]];

#pragma unroll
        for (int mt = 0; mt < 2; mt++)
#pragma unroll
            for (int nt = 0; nt < 8; nt++)
#pragma unroll
                for (int rr = 0; rr < 2; rr++) {
                    float a = alpha[mt * 2 + rr];
                    acc_o[mt][nt][2 * rr]     *= a;
                    acc_o[mt][nt][2 * rr + 1] *= a;
                }

#pragma unroll
        for (int ks = 0; ks < 4; ks++) {
            const uint32_t kB = ks * 32;
            uint32_t a[2][4];
            ldsm_x4(a[0], smem + FL_P + aP[0] + kB);
            ldsm_x4(a[1], smem + FL_P + aP[1] + kB);
#pragma unroll
            for (int p = 0; p < 4; p++) {
                uint32_t bh[4];
                ldsm_x4(bh, smem + FL_V + bV[p] + kB);
#pragma unroll
                for (int sub = 0; sub < 2; sub++) {
                    const int nt = 2 * p + sub;
#pragma unroll
                    for (int mt = 0; mt < 2; mt++)
                        mma_fp16(acc_o[mt][nt], a[mt], bh + 2 * sub);
                }
            }
        }
        __syncthreads();

        if (kb + 1 < 32) { load_V(kb + 1);         CP_COMMIT(); }
        if (kb + 2 < 32) { load_K(kb + 2, kb & 1); CP_COMMIT(); }
    }

    __half* Ob = Oh + (long long)bb * S_ * (NH_ * DV_) + hh * DV_;
#pragma unroll
    for (int mt = 0; mt < 2; mt++)
#pragma unroll
        for (int rr = 0; rr < 2; rr++) {
            int sl = mt * 2 + rr;
            float inv = 1.f / l_st[sl];
            long long row = q0 + rowi[sl];
#pragma unroll
            for (int nt = 0; nt < 8; nt++) {
                int col = wk * 64 + nt * 8 + fc;
                *(__half2*)(Ob + row * (NH_ * DV_) + col) =
                    __floats2half2_rn(acc_o[mt][nt][2 * rr] * inv,
                                      acc_o[mt][nt][2 * rr + 1] * inv);
            }
        }
}

// ---------------- fp32 -> fp16, vectorized 8 elems/thread ----------------
__global__ void convert_h_kernel(const float* __restrict__ x,
                                 __half* __restrict__ h, long long n)
{
    long long i = ((long long)blockIdx.x * 256 + threadIdx.x) * 8;
    if (i < n) {
        float4 a = *(const float4*)(x + i);
        float4 b = *(const float4*)(x + i + 4);
        uint4 o;
        o.x = pack_h2(a.x, a.y);
        o.y = pack_h2(a.z, a.w);
        o.z = pack_h2(b.x, b.y);
        o.w = pack_h2(b.z, b.w);
        *(uint4*)(h + i) = o;
    }
}

// ---------------- RMSNorm -> fp16, vectorized ----------------
__global__ void __launch_bounds__(256)
rmsnorm_h_kernel(const float* __restrict__ x, int ldx, const float* __restrict__ w,
                 __half* __restrict__ yh, int ldy, int cols)
{
    const int row = blockIdx.x;
    const float* xr = x + (long long)row * ldx;
    float ss = 0.f;
    for (int c = threadIdx.x * 4; c < cols; c += 1024) {
        float4 v = *(const float4*)(xr + c);
        ss += v.x * v.x + v.y * v.y + v.z * v.z + v.w * v.w;
    }
    __shared__ float red[256];
    red[threadIdx.x] = ss;
    __syncthreads();
    for (int s = 128; s > 0; s >>= 1) {
        if (threadIdx.x < s) red[threadIdx.x] += red[threadIdx.x + s];
        __syncthreads();
    }
    float inv = 1.f / sqrtf(red[0] / (float)cols + 1e-6f);
    long long base = (long long)row * ldy;
    for (int c = threadIdx.x * 4; c < cols; c += 1024) {
        float4 v = *(const float4*)(xr + c);
        float4 wv = *(const float4*)(w + c);
        uint2 o;
        o.x = pack_h2(wv.x * v.x * inv, wv.y * v.y * inv);
        o.y = pack_h2(wv.z * v.z * inv, wv.w * v.w * inv);
        *(uint2*)(yh + base + c) = o;
    }
}

// ---------------- RoPE ----------------
__global__ void freqs_kernel(float* __restrict__ cosd, float* __restrict__ sind)
{
    int t = blockIdx.x, i = threadIdx.x;
    double inv = pow(10000.0, -(double)(2 * i) / (double)DROPE);
    double f = (double)t * inv;
    cosd[t * 32 + i] = (float)cos(f);
    sind[t * 32 + i] = (float)sin(f);
}

// fused: rope on q_pe dims + fp16 convert of full q row -> q_h (8 floats/thread)
__global__ void __launch_bounds__(256)
rope_q_convert_kernel(const float* __restrict__ q, __half* __restrict__ qh,
                      const float* __restrict__ cosd, const float* __restrict__ sind)
{
    int m = blockIdx.x;
    int t = m & (S_ - 1);
    long long base = (long long)m * (NH_ * DQK);
    const float* ct = cosd + t * 32;
    const float* st = sind + t * 32;
#pragma unroll
    for (int j = 0; j < 2; j++) {
        int g = threadIdx.x + 256 * j;           // group of 8 floats; 384 groups
        if (g >= 384) break;
        int col = g * 8;
        int d = col % DQK;
        float4 a = *(const float4*)(q + base + col);
        float4 b = *(const float4*)(q + base + col + 4);
        if (d >= DNOPE) {
            int i0 = (d - DNOPE) >> 1;
            float v[8] = {a.x, a.y, a.z, a.w, b.x, b.y, b.z, b.w};
#pragma unroll
            for (int p = 0; p < 4; p++) {
                float cs = ct[i0 + p], sn = st[i0 + p];
                float e = v[2 * p], o = v[2 * p + 1];
                v[2 * p]     = e * cs - o * sn;
                v[2 * p + 1] = e * sn + o * cs;
            }
            a = make_float4(v[0], v[1], v[2], v[3]);
            b = make_float4(v[4], v[5], v[6], v[7]);
        }
        uint4 o;
        o.x = pack_h2(a.x, a.y);
        o.y = pack_h2(a.z, a.w);
        o.z = pack_h2(b.x, b.y);
        o.w = pack_h2(b.z, b.w);
        *(uint4*)(qh + base + col) = o;
    }
}

__global__ void rope_k_kernel(const float* __restrict__ kv, float* __restrict__ kpe,
                              const float* __restrict__ cosd, const float* __restrict__ sind)
{
    int m = blockIdx.x;
    int t = m & (S_ - 1);
    int i = threadIdx.x;
    float cs = cosd[t * 32 + i], sn = sind[t * 32 + i];
    long long base = (long long)m * (KVLORA + DROPE) + KVLORA + 2 * i;
    float e = kv[base], o = kv[base + 1];
    kpe[m * DROPE + 2 * i]     = e * cs - o * sn;
    kpe[m * DROPE + 2 * i + 1] = e * sn + o * cs;
}

// ---------------- kf assembly (fp16), 8 elems/thread ----------------
__global__ void build_kf_kernel(const float* __restrict__ kvx, const float* __restrict__ kpe,
                                __half* __restrict__ kfh)
{
    long long idx = (long long)blockIdx.x * 256 + threadIdx.x;  // group id < M_*384
    int g = (int)(idx % 384);
    long long m = idx / 384;
    int col = g * 8;
    int h = col / DQK, d = col % DQK;
    const float* src = (d < DNOPE)
        ? kvx + m * (NH_ * (DNOPE + DV_)) + h * (DNOPE + DV_) + d
        : kpe + m * DROPE + (d - DNOPE);
    float4 a = *(const float4*)(src);
    float4 b = *(const float4*)(src + 4);
    uint4 o;
    o.x = pack_h2(a.x, a.y);
    o.y = pack_h2(a.z, a.w);
    o.z = pack_h2(b.x, b.y);
    o.w = pack_h2(b.z, b.w);
    *(uint4*)(kfh + (long long)m * (NH_ * DQK) + col) = o;
}

// ---------------- V extraction + transpose: vt[b][h][d][s] ----------------
__global__ void __launch_bounds__(256)
transpose_v_kernel(const float* __restrict__ kvx, __half* __restrict__ vth)
{
    __shared__ float t[32][33];
    int z = blockIdx.z;
    int b = z / NH_, h = z % NH_;
    int s0 = blockIdx.x * 32, d0 = blockIdx.y * 32;
    int tx = threadIdx.x & 31, ty = threadIdx.x >> 5;
#pragma unroll
    for (int i = ty; i < 32; i += 8)
        t[i][tx] = kvx[((long long)(b * S_ + s0 + i)) * (NH_ * (DNOPE + DV_))
                       + h * (DNOPE + DV_) + DNOPE + d0 + tx];
    __syncthreads();
#pragma unroll
    for (int i = ty; i < 32; i += 8) {
        long long o = ((long long)z * DV_ + d0 + i) * S_ + s0 + tx;
        vth[o] = __float2half_rn(t[tx][i]);
    }
}

// ---------------- launch ----------------
extern "C" void kernel_launch(void* const* d_in, const int* in_sizes, int n_in,
                              void* d_out, int out_size)
{
    const float* hs        = (const float*)d_in[0];
    const float* wq_a      = (const float*)d_in[1];
    const float* q_norm_w  = (const float*)d_in[2];
    const float* wq_b      = (const float*)d_in[3];
    const float* wkv_a     = (const float*)d_in[4];
    const float* kv_norm_w = (const float*)d_in[5];
    const float* wkv_b     = (const float*)d_in[6];
    const float* wo        = (const float*)d_in[7];
    float* out = (float*)d_out;

    cudaFuncSetAttribute(hgemm, cudaFuncAttributeMaxDynamicSharedMemorySize, GEMM_SMEM);
    cudaFuncSetAttribute(flash_attn, cudaFuncAttributeMaxDynamicSharedMemorySize, FL_SMEM);

    float *p_qa, *p_q, *p_kv, *p_kpe, *p_kvx, *p_cos, *p_sin;
    cudaGetSymbolAddress((void**)&p_qa,  g_qa);
    cudaGetSymbolAddress((void**)&p_q,   g_q);
    cudaGetSymbolAddress((void**)&p_kv,  g_kv);
    cudaGetSymbolAddress((void**)&p_kpe, g_kpe);
    cudaGetSymbolAddress((void**)&p_kvx, g_kvx);
    cudaGetSymbolAddress((void**)&p_cos, g_cos);
    cudaGetSymbolAddress((void**)&p_sin, g_sin);

    __half *hs_h, *wqa_h, *wqb_h, *wkva_h, *wkvb_h, *wo_h, *qa_h, *q_h;
    __half *kvc_h, *kf_h, *vt_h, *ao_h;
    cudaGetSymbolAddress((void**)&hs_h,  g_hs_h);
    cudaGetSymbolAddress((void**)&wqa_h, g_wqa_h);
    cudaGetSymbolAddress((void**)&wqb_h, g_wqb_h);
    cudaGetSymbolAddress((void**)&wkva_h, g_wkva_h);
    cudaGetSymbolAddress((void**)&wkvb_h, g_wkvb_h);
    cudaGetSymbolAddress((void**)&wo_h,  g_wo_h);
    cudaGetSymbolAddress((void**)&qa_h,  g_qa_h);
    cudaGetSymbolAddress((void**)&q_h,   g_qh);
    cudaGetSymbolAddress((void**)&kvc_h, g_kvc_h);
    cudaGetSymbolAddress((void**)&kf_h,  g_kf_h);
    cudaGetSymbolAddress((void**)&vt_h,  g_vt_h);
    cudaGetSymbolAddress((void**)&ao_h,  g_ao_h);

    const float scale = 1.0f / sqrtf((float)DQK);
    auto cv8 = [](long long n) { return (int)((n / 8 + 255) / 256); };
    auto ntiles = [](int n) { return (n + 127) / 128; };

    freqs_kernel<<<S_, 32>>>(p_cos, p_sin);

    convert_h_kernel<<<cv8((long long)M_ * H_), 256>>>(hs, hs_h, (long long)M_ * H_);
    convert_h_kernel<<<cv8((long long)QLORA * H_), 256>>>(wq_a, wqa_h, (long long)QLORA * H_);
    convert_h_kernel<<<cv8((long long)NH_ * DQK * QLORA), 256>>>(wq_b, wqb_h, (long long)NH_ * DQK * QLORA);
    convert_h_kernel<<<cv8((long long)(KVLORA + DROPE) * H_), 256>>>(wkv_a, wkva_h, (long long)(KVLORA + DROPE) * H_);
    convert_h_kernel<<<cv8((long long)NH_ * (DNOPE + DV_) * KVLORA), 256>>>(wkv_b, wkvb_h, (long long)NH_ * (DNOPE + DV_) * KVLORA);
    convert_h_kernel<<<cv8((long long)H_ * NH_ * DV_), 256>>>(wo, wo_h, (long long)H_ * NH_ * DV_);

    // q_a = hs @ wq_a^T   [4096 x 1536] K=2048
    hgemm<<<dim3(ntiles(QLORA), M_ / 128, 1), 256, GEMM_SMEM>>>(
        hs_h, wqa_h, p_qa, QLORA, H_, H_, H_, QLORA, 1.f);

    rmsnorm_h_kernel<<<M_, 256>>>(p_qa, QLORA, q_norm_w, qa_h, QLORA, QLORA);

    // q = q_a @ wq_b^T    [4096 x 3072] K=1536
    hgemm<<<dim3(ntiles(NH_ * DQK), M_ / 128, 1), 256, GEMM_SMEM>>>(
        qa_h, wqb_h, p_q, NH_ * DQK, QLORA, QLORA, QLORA, NH_ * DQK, 1.f);

    // kv = hs @ wkv_a^T   [4096 x 576] K=2048
    hgemm<<<dim3(ntiles(KVLORA + DROPE), M_ / 128, 1), 256, GEMM_SMEM>>>(
        hs_h, wkva_h, p_kv, KVLORA + DROPE, H_, H_, H_, KVLORA + DROPE, 1.f);

    rmsnorm_h_kernel<<<M_, 256>>>(p_kv, KVLORA + DROPE, kv_norm_w, kvc_h, KVLORA, KVLORA);
    rope_k_kernel<<<M_, 32>>>(p_kv, p_kpe, p_cos, p_sin);

    // kv_x = kv_c @ wkv_b^T  [4096 x 4096] K=512
    hgemm<<<dim3(ntiles(NH_ * (DNOPE + DV_)), M_ / 128, 1), 256, GEMM_SMEM>>>(
        kvc_h, wkvb_h, p_kvx, NH_ * (DNOPE + DV_), KVLORA, KVLORA, KVLORA,
        NH_ * (DNOPE + DV_), 1.f);

    rope_q_convert_kernel<<<M_, 256>>>(p_q, q_h, p_cos, p_sin);
    build_kf_kernel<<<(int)(((long long)M_ * 384 + 255) / 256), 256>>>(p_kvx, p_kpe, kf_h);
    transpose_v_kernel<<<dim3(S_ / 32, DV_ / 32, B_ * NH_), 256>>>(p_kvx, vt_h);

    // fused attention: ao_h = softmax(scale * Q Kf^T) V
    flash_attn<<<dim3(S_ / 128, B_ * NH_), 256, FL_SMEM>>>(
        q_h, kf_h, vt_h, ao_h, scale);

    // out = ao @ wo^T   [4096 x 2048] K=2048
    hgemm<<<dim3(ntiles(H_), M_ / 128, 1), 256, GEMM_SMEM>>>(
        ao_h, wo_h, out, H_, NH_ * DV_, NH_ * DV_, NH_ * DV_, H_, 1.f);
}

// round 15
// speedup vs baseline: 1.1682x; 1.0615x over previous
#include <cuda_runtime.h>
#include <cuda_fp16.h>
#include <math.h>
#include <stdint.h>

// ---------------- problem constants ----------------
#define B_    2
#define S_    2048
#define H_    2048
#define NH_   16
#define QLORA 1536
#define KVLORA 512
#define DNOPE 128
#define DROPE 64
#define DV_   128
#define DQK   192
#define M_    (B_ * S_)    // 4096

// ---------------- fp32 scratch ----------------
__device__ __align__(16) float g_qa  [(size_t)M_ * QLORA];
__device__ __align__(16) float g_kv  [(size_t)M_ * (KVLORA + DROPE)];
__device__ float g_cos [S_ * (DROPE / 2)];
__device__ float g_sin [S_ * (DROPE / 2)];

// ---------------- fp16 operand buffers ----------------
__device__ __align__(16) __half g_hs_h [(size_t)M_ * H_];
__device__ __align__(16) __half g_wqa_h[(size_t)QLORA * H_];
__device__ __align__(16) __half g_wqb_h[(size_t)NH_ * DQK * QLORA];
__device__ __align__(16) __half g_wkva_h[(size_t)(KVLORA + DROPE) * H_];
__device__ __align__(16) __half g_wkvb_h[(size_t)NH_ * (DNOPE + DV_) * KVLORA];
__device__ __align__(16) __half g_wo_h [(size_t)H_ * NH_ * DV_];
__device__ __align__(16) __half g_qa_h [(size_t)M_ * QLORA];
__device__ __align__(16) __half g_qh   [(size_t)M_ * NH_ * DQK];
__device__ __align__(16) __half g_kvc_h[(size_t)M_ * KVLORA];
__device__ __align__(16) __half g_kpe_h[(size_t)M_ * DROPE];
__device__ __align__(16) __half g_kvx_h[(size_t)M_ * (NH_ * (DNOPE + DV_))];
__device__ __align__(16) __half g_vt_h [(size_t)B_ * NH_ * DV_ * S_];
__device__ __align__(16) __half g_ao_h [(size_t)M_ * NH_ * DV_];

// ---------------- helpers ----------------
__device__ __forceinline__ uint32_t smem_u32(const void* p) {
    uint32_t a;
    asm("{ .reg .u64 t; cvta.to.shared.u64 t, %1; cvt.u32.u64 %0, t; }" : "=r"(a) : "l"(p));
    return a;
}

__device__ __forceinline__ void cp16(uint32_t dst, const void* src, bool pred) {
    int sz = pred ? 16 : 0;
    asm volatile("cp.async.cg.shared.global [%0], [%1], 16, %2;\n"
                 :: "r"(dst), "l"(src), "r"(sz));
}
#define CP_COMMIT()   asm volatile("cp.async.commit_group;\n" ::: "memory")
#define CP_WAIT(n)    asm volatile("cp.async.wait_group %0;\n" :: "n"(n) : "memory")

__device__ __forceinline__ void mma_fp16(float* c, const uint32_t* a, const uint32_t* b) {
    asm volatile(
        "mma.sync.aligned.m16n8k16.row.col.f32.f16.f16.f32 "
        "{%0,%1,%2,%3}, {%4,%5,%6,%7}, {%8,%9}, {%0,%1,%2,%3};\n"
        : "+f"(c[0]), "+f"(c[1]), "+f"(c[2]), "+f"(c[3])
        : "r"(a[0]), "r"(a[1]), "r"(a[2]), "r"(a[3]), "r"(b[0]), "r"(b[1]));
}

__device__ __forceinline__ void ldsm_x4(uint32_t* r, uint32_t addr) {
    asm volatile("ldmatrix.sync.aligned.m8n8.x4.shared.b16 {%0,%1,%2,%3}, [%4];"
        : "=r"(r[0]), "=r"(r[1]), "=r"(r[2]), "=r"(r[3]) : "r"(addr));
}

__device__ __forceinline__ uint32_t pack_h2(float a, float b) {
    __half2 h = __floats2half2_rn(a, b);
    return *(uint32_t*)&h;
}

// ---------------- persistent pipelined fp16 tensor-core GEMM, tile 128x128 ----------------
// C[m,n] = sum_k A[m,k] * B[n,k]   (B row-major [n][k], K-contiguous)
// 256 threads, K-chunk 32, 3-stage cp.async, 2 CTA/SM. Grid = min(tiles, 296);
// each CTA loops over tiles (kills wave quantization).
// mode 0: fp32 C.  mode 1: fp16 C with fused RoPE on d>=128 (q path).  mode 2: fp16 C.
#define STG_A   0
#define STG_B   10240
#define STG_BYTES 20480
#define GEMM_SMEM (3 * STG_BYTES)

extern __shared__ char sm_raw[];

__global__ void __launch_bounds__(256, 2)
hgemm(const __half* __restrict__ A,
      const __half* __restrict__ B,
      void* __restrict__ Cv,
      int N, int K, int lda, int ldb, int ldc,
      int ntx, int nty, int mode,
      const float* __restrict__ cosd, const float* __restrict__ sind)
{
    const int tid = threadIdx.x;
    const int lane = tid & 31, w = tid >> 5;
    const int wm = (w >> 1) * 32, wn = (w & 1) * 64;
    const int fr = lane >> 2, fc = (lane & 3) * 2;
    const int nk = K >> 5;

    const uint32_t smem = smem_u32(sm_raw);

    uint32_t aoff[2], boff[4];
    {
        int r = wm + (lane & 15);
        int c = (lane >> 4) * 8;
        aoff[0] = (uint32_t)((r * 40 + c) * 2);
        aoff[1] = (uint32_t)(((r + 16) * 40 + c) * 2);
        int lnB = lane & 7;
        int pHi = lane >> 4;
        int kh  = ((lane >> 3) & 1) * 8;
#pragma unroll
        for (int p = 0; p < 4; p++) {
            int n = wn + (2 * p + pHi) * 8 + lnB;
            boff[p] = (uint32_t)((n * 40 + kh) * 2);
        }
    }

    const int lrow0 = tid >> 2, lch = tid & 3;
    const uint32_t so1 = (uint32_t)(lrow0 * 80 + lch * 16);
    const uint32_t so2 = (uint32_t)((lrow0 + 64) * 80 + lch * 16);
    const int ntiles = ntx * nty;

    for (int tile = blockIdx.x; tile < ntiles; tile += gridDim.x) {
        const int m0 = (tile / ntx) * 128;
        const int n0 = (tile % ntx) * 128;

        const __half* gA  = A + (long long)(m0 + lrow0) * lda + lch * 8;
        const __half* gA2 = gA + 64ll * lda;
        const bool bp1 = (n0 + lrow0) < N;
        const bool bp2 = (n0 + lrow0 + 64) < N;
        const __half* gB  = B + (long long)(n0 + (bp1 ? lrow0 : 0)) * ldb + lch * 8;
        const __half* gB2 = B + (long long)(n0 + (bp2 ? lrow0 + 64 : 0)) * ldb + lch * 8;

        auto load_stage = [&](int kc, int st) {
            uint32_t sb = smem + st * STG_BYTES;
            cp16(sb + STG_A + so1, gA  + kc, true);
            cp16(sb + STG_A + so2, gA2 + kc, true);
            cp16(sb + STG_B + so1, gB  + kc, bp1);
            cp16(sb + STG_B + so2, gB2 + kc, bp2);
            CP_COMMIT();
        };

        float acc[2][8][4] = {};

        load_stage(0, 0);
        if (nk > 1) load_stage(32, 1); else CP_COMMIT();

        for (int k = 0; k < nk; k++) {
            const int st = k % 3;
            if (k + 2 < nk) load_stage((k + 2) * 32, (k + 2) % 3);
            else CP_COMMIT();
            CP_WAIT(2);
            __syncthreads();

            const uint32_t sb = smem + st * STG_BYTES;

#pragma unroll
            for (int ks = 0; ks < 2; ks++) {
                const uint32_t kB = ks * 32;
                uint32_t a[2][4];
#pragma unroll
                for (int mt = 0; mt < 2; mt++)
                    ldsm_x4(a[mt], sb + STG_A + aoff[mt] + kB);
#pragma unroll
                for (int p = 0; p < 4; p++) {
                    uint32_t bh[4];
                    ldsm_x4(bh, sb + STG_B + boff[p] + kB);
#pragma unroll
                    for (int sub = 0; sub < 2; sub++) {
                        const int nt = 2 * p + sub;
#pragma unroll
                        for (int mt = 0; mt < 2; mt++)
                            mma_fp16(acc[mt][nt], a[mt], bh + 2 * sub);
                    }
                }
            }
            __syncthreads();
        }

        // ---- epilogue ----
        if (mode == 0) {
            float* C = (float*)Cv;
#pragma unroll
            for (int mt = 0; mt < 2; mt++) {
                int row = m0 + wm + mt * 16 + fr;
#pragma unroll
                for (int nt = 0; nt < 8; nt++) {
                    int col = n0 + wn + nt * 8 + fc;
                    if (col < N) {
                        C[(long long)row * ldc + col]           = acc[mt][nt][0];
                        C[(long long)row * ldc + col + 1]       = acc[mt][nt][1];
                        C[(long long)(row + 8) * ldc + col]     = acc[mt][nt][2];
                        C[(long long)(row + 8) * ldc + col + 1] = acc[mt][nt][3];
                    }
                }
            }
        } else {
            __half* C = (__half*)Cv;
#pragma unroll
            for (int mt = 0; mt < 2; mt++) {
                int row = m0 + wm + mt * 16 + fr;
#pragma unroll
                for (int nt = 0; nt < 8; nt++) {
                    int col = n0 + wn + nt * 8 + fc;
                    if (col >= N) continue;
                    float c0 = acc[mt][nt][0], c1 = acc[mt][nt][1];
                    float c2 = acc[mt][nt][2], c3 = acc[mt][nt][3];
                    if (mode == 1) {
                        int d = col % DQK;
                        if (d >= DNOPE) {
                            int i = (d - DNOPE) >> 1;
                            int t0 = row & (S_ - 1), t1 = (row + 8) & (S_ - 1);
                            float cs0 = cosd[t0 * 32 + i], sn0 = sind[t0 * 32 + i];
                            float cs1 = cosd[t1 * 32 + i], sn1 = sind[t1 * 32 + i];
                            float r0 = c0 * cs0 - c1 * sn0, i0 = c0 * sn0 + c1 * cs0;
                            float r1 = c2 * cs1 - c3 * sn1, i1 = c2 * sn1 + c3 * cs1;
                            c0 = r0; c1 = i0; c2 = r1; c3 = i1;
                        }
                    }
                    *(__half2*)(C + (long long)row * ldc + col) = __floats2half2_rn(c0, c1);
                    *(__half2*)(C + (long long)(row + 8) * ldc + col) = __floats2half2_rn(c2, c3);
                }
            }
        }
    }
}

// ---------------- fused flash attention ----------------
// K loaded directly from kvx_h (nope) + kpe_h (rope) — no kf buffer.
#define FL_Q    0
#define FL_K    51200
#define FL_KS   25600
#define FL_V    102400
#define FL_P    120832
#define FL_RED  139264
#define FL_SMEM 141312

__global__ void __launch_bounds__(256, 1)
flash_attn(const __half* __restrict__ Qg,
           const __half* __restrict__ Kvx,
           const __half* __restrict__ Kpe,
           const __half* __restrict__ Vh,
           __half* __restrict__ Oh, float scale)
{
    const int z  = blockIdx.y;
    const int bb = z >> 4, hh = z & 15;
    const int q0 = blockIdx.x * 128;
    const int tid = threadIdx.x, lane = tid & 31, w = tid >> 5;
    const int wq = w >> 1, wk = w & 1;
    const int fr = lane >> 2, fc = (lane & 3) * 2;

    const uint32_t smem = smem_u32(sm_raw);

    const __half* Qb  = Qg + (long long)bb * S_ * (NH_ * DQK) + hh * DQK;
    const __half* Kvb = Kvx + (long long)bb * S_ * (NH_ * (DNOPE + DV_)) + hh * (DNOPE + DV_);
    const __half* Kpb = Kpe + (long long)bb * S_ * DROPE;
    const __half* Vhb = Vh + (long long)z * DV_ * S_;

    auto load_Q = [&]() {
#pragma unroll
        for (int j = 0; j < 12; j++) {
            int idx = tid + 256 * j;
            int r = idx / 24, ch = idx % 24;
            cp16(smem + FL_Q + (uint32_t)(r * 200 + ch * 8) * 2,
                 Qb + (long long)(q0 + r) * (NH_ * DQK) + ch * 8, true);
        }
    };
    auto load_K = [&](int kb, int st) {
        uint32_t base = smem + FL_K + st * FL_KS;
#pragma unroll
        for (int j = 0; j < 6; j++) {
            int idx = tid + 256 * j;
            int r = idx / 24, ch = idx % 24;
            uint32_t so = (uint32_t)(r * 200 + ch * 8) * 2;
            if (ch < 16)
                cp16(base + so, Kvb + (long long)(kb * 64 + r) * (NH_ * (DNOPE + DV_)) + ch * 8, true);
            else
                cp16(base + so, Kpb + (long long)(kb * 64 + r) * DROPE + (ch - 16) * 8, true);
        }
    };
    auto load_V = [&](int kb) {
#pragma unroll
        for (int j = 0; j < 4; j++) {
            int idx = tid + 256 * j;
            int d = idx >> 3, ch = idx & 7;
            cp16(smem + FL_V + (uint32_t)(d * 72 + ch * 8) * 2,
                 Vhb + (long long)d * S_ + kb * 64 + ch * 8, true);
        }
    };

    uint32_t aQ[2], aP[2], bK[2], bV[4];
    {
        int r = wq * 32 + (lane & 15);
        int c = (lane >> 4) * 8;
        aQ[0] = (uint32_t)((r * 200 + c) * 2);
        aQ[1] = (uint32_t)(((r + 16) * 200 + c) * 2);
        aP[0] = (uint32_t)((r * 72 + c) * 2);
        aP[1] = (uint32_t)(((r + 16) * 72 + c) * 2);
        int lnB = lane & 7, pHi = lane >> 4, kh = ((lane >> 3) & 1) * 8;
#pragma unroll
        for (int p = 0; p < 2; p++) {
            int n = wk * 32 + (2 * p + pHi) * 8 + lnB;
            bK[p] = (uint32_t)((n * 200 + kh) * 2);
        }
#pragma unroll
        for (int p = 0; p < 4; p++) {
            int n = wk * 64 + (2 * p + pHi) * 8 + lnB;
            bV[p] = (uint32_t)((n * 72 + kh) * 2);
        }
    }

    float acc_o[2][8][4] = {};
    float m_st[4], l_st[4];
#pragma unroll
    for (int i = 0; i < 4; i++) { m_st[i] = -1e30f; l_st[i] = 0.f; }

    float* redm = (float*)(sm_raw + FL_RED);
    float* reds = (float*)(sm_raw + FL_RED + 1024);
    int rowi[4];
#pragma unroll
    for (int mt = 0; mt < 2; mt++)
#pragma unroll
        for (int rr = 0; rr < 2; rr++)
            rowi[mt * 2 + rr] = wq * 32 + mt * 16 + rr * 8 + fr;

    load_Q(); load_K(0, 0); CP_COMMIT();
    load_V(0);              CP_COMMIT();
    load_K(1, 1);           CP_COMMIT();

    for (int kb = 0; kb < 32; kb++) {
        if (kb == 31) { CP_WAIT(1); } else { CP_WAIT(2); }
        __syncthreads();

        float acc_s[2][4][4] = {};
        const uint32_t kbase = smem + FL_K + (kb & 1) * FL_KS;
#pragma unroll
        for (int ks = 0; ks < 12; ks++) {
            const uint32_t kB = ks * 32;
            uint32_t a[2][4];
            ldsm_x4(a[0], smem + FL_Q + aQ[0] + kB);
            ldsm_x4(a[1], smem + FL_Q + aQ[1] + kB);
#pragma unroll
            for (int p = 0; p < 2; p++) {
                uint32_t bh[4];
                ldsm_x4(bh, kbase + bK[p] + kB);
#pragma unroll
                for (int sub = 0; sub < 2; sub++) {
                    const int nt = 2 * p + sub;
#pragma unroll
                    for (int mt = 0; mt < 2; mt++)
                        mma_fp16(acc_s[mt][nt], a[mt], bh + 2 * sub);
                }
            }
        }
#pragma unroll
        for (int mt = 0; mt < 2; mt++)
#pragma unroll
            for (int nt = 0; nt < 4; nt++)
#pragma unroll
                for (int c = 0; c < 4; c++) acc_s[mt][nt][c] *= scale;

#pragma unroll
        for (int sl = 0; sl < 4; sl++) {
            int mt = sl >> 1, rr = sl & 1;
            float v = -1e30f;
#pragma unroll
            for (int nt = 0; nt < 4; nt++) {
                v = fmaxf(v, acc_s[mt][nt][2 * rr]);
                v = fmaxf(v, acc_s[mt][nt][2 * rr + 1]);
            }
            v = fmaxf(v, __shfl_xor_sync(0xffffffffu, v, 1));
            v = fmaxf(v, __shfl_xor_sync(0xffffffffu, v, 2));
            if ((lane & 3) == 0) redm[wk * 128 + rowi[sl]] = v;
        }
        __syncthreads();

        float alpha[4];
#pragma unroll
        for (int sl = 0; sl < 4; sl++) {
            float bm = fmaxf(redm[rowi[sl]], redm[128 + rowi[sl]]);
            float mn = fmaxf(m_st[sl], bm);
            alpha[sl] = __expf(m_st[sl] - mn);
            m_st[sl] = mn;
        }

#pragma unroll
        for (int sl = 0; sl < 4; sl++) {
            int mt = sl >> 1, rr = sl & 1;
            int prow = rowi[sl];
            float s = 0.f;
#pragma unroll
            for (int nt = 0; nt < 4; nt++) {
                float p0 = __expf(acc_s[mt][nt][2 * rr]     - m_st[sl]);
                float p1 = __expf(acc_s[mt][nt][2 * rr + 1] - m_st[sl]);
                s += p0 + p1;
                *(__half2*)(sm_raw + FL_P + (prow * 72 + wk * 32 + nt * 8 + fc) * 2)
                    = __floats2half2_rn(p0, p1);
            }
            s += __shfl_xor_sync(0xffffffffu, s, 1);
            s += __shfl_xor_sync(0xffffffffu, s, 2);
            if ((lane & 3) == 0) reds[wk * 128 + prow] = s;
        }

        if (kb == 31) { CP_WAIT(0); } else { CP_WAIT(1); }
        __syncthreads();

#pragma unroll
        for (int sl = 0; sl < 4; sl++)
            l_st[sl] = alpha[sl] * l_st[sl] + reds[rowi[sl]] + reds[128 + rowi[sl]];

#pragma unroll
        for (int mt = 0; mt < 2; mt++)
#pragma unroll
            for (int nt = 0; nt < 8; nt++)
#pragma unroll
                for (int rr = 0; rr < 2; rr++) {
                    float a = alpha[mt * 2 + rr];
                    acc_o[mt][nt][2 * rr]     *= a;
                    acc_o[mt][nt][2 * rr + 1] *= a;
                }

#pragma unroll
        for (int ks = 0; ks < 4; ks++) {
            const uint32_t kB = ks * 32;
            uint32_t a[2][4];
            ldsm_x4(a[0], smem + FL_P + aP[0] + kB);
            ldsm_x4(a[1], smem + FL_P + aP[1] + kB);
#pragma unroll
            for (int p = 0; p < 4; p++) {
                uint32_t bh[4];
                ldsm_x4(bh, smem + FL_V + bV[p] + kB);
#pragma unroll
                for (int sub = 0; sub < 2; sub++) {
                    const int nt = 2 * p + sub;
#pragma unroll
                    for (int mt = 0; mt < 2; mt++)
                        mma_fp16(acc_o[mt][nt], a[mt], bh + 2 * sub);
                }
            }
        }
        __syncthreads();

        if (kb + 1 < 32) { load_V(kb + 1);         CP_COMMIT(); }
        if (kb + 2 < 32) { load_K(kb + 2, kb & 1); CP_COMMIT(); }
    }

    __half* Ob = Oh + (long long)bb * S_ * (NH_ * DV_) + hh * DV_;
#pragma unroll
    for (int mt = 0; mt < 2; mt++)
#pragma unroll
        for (int rr = 0; rr < 2; rr++) {
            int sl = mt * 2 + rr;
            float inv = 1.f / l_st[sl];
            long long row = q0 + rowi[sl];
#pragma unroll
            for (int nt = 0; nt < 8; nt++) {
                int col = wk * 64 + nt * 8 + fc;
                *(__half2*)(Ob + row * (NH_ * DV_) + col) =
                    __floats2half2_rn(acc_o[mt][nt][2 * rr] * inv,
                                      acc_o[mt][nt][2 * rr + 1] * inv);
            }
        }
}

// ---------------- fp32 -> fp16, vectorized 8 elems/thread ----------------
__global__ void convert_h_kernel(const float* __restrict__ x,
                                 __half* __restrict__ h, long long n)
{
    long long i = ((long long)blockIdx.x * 256 + threadIdx.x) * 8;
    if (i < n) {
        float4 a = *(const float4*)(x + i);
        float4 b = *(const float4*)(x + i + 4);
        uint4 o;
        o.x = pack_h2(a.x, a.y);
        o.y = pack_h2(a.z, a.w);
        o.z = pack_h2(b.x, b.y);
        o.w = pack_h2(b.z, b.w);
        *(uint4*)(h + i) = o;
    }
}

// ---------------- RMSNorm -> fp16, vectorized ----------------
__global__ void __launch_bounds__(256)
rmsnorm_h_kernel(const float* __restrict__ x, int ldx, const float* __restrict__ w,
                 __half* __restrict__ yh, int ldy, int cols)
{
    const int row = blockIdx.x;
    const float* xr = x + (long long)row * ldx;
    float ss = 0.f;
    for (int c = threadIdx.x * 4; c < cols; c += 1024) {
        float4 v = *(const float4*)(xr + c);
        ss += v.x * v.x + v.y * v.y + v.z * v.z + v.w * v.w;
    }
    __shared__ float red[256];
    red[threadIdx.x] = ss;
    __syncthreads();
    for (int s = 128; s > 0; s >>= 1) {
        if (threadIdx.x < s) red[threadIdx.x] += red[threadIdx.x + s];
        __syncthreads();
    }
    float inv = 1.f / sqrtf(red[0] / (float)cols + 1e-6f);
    long long base = (long long)row * ldy;
    for (int c = threadIdx.x * 4; c < cols; c += 1024) {
        float4 v = *(const float4*)(xr + c);
        float4 wv = *(const float4*)(w + c);
        uint2 o;
        o.x = pack_h2(wv.x * v.x * inv, wv.y * v.y * inv);
        o.y = pack_h2(wv.z * v.z * inv, wv.w * v.w * inv);
        *(uint2*)(yh + base + c) = o;
    }
}

// ---------------- RoPE ----------------
__global__ void freqs_kernel(float* __restrict__ cosd, float* __restrict__ sind)
{
    int t = blockIdx.x, i = threadIdx.x;
    double inv = pow(10000.0, -(double)(2 * i) / (double)DROPE);
    double f = (double)t * inv;
    cosd[t * 32 + i] = (float)cos(f);
    sind[t * 32 + i] = (float)sin(f);
}

// rope on k_pe -> fp16
__global__ void rope_k_kernel(const float* __restrict__ kv, __half* __restrict__ kpeh,
                              const float* __restrict__ cosd, const float* __restrict__ sind)
{
    int m = blockIdx.x;
    int t = m & (S_ - 1);
    int i = threadIdx.x;
    float cs = cosd[t * 32 + i], sn = sind[t * 32 + i];
    long long base = (long long)m * (KVLORA + DROPE) + KVLORA + 2 * i;
    float e = kv[base], o = kv[base + 1];
    *(__half2*)(kpeh + (long long)m * DROPE + 2 * i) =
        __floats2half2_rn(e * cs - o * sn, e * sn + o * cs);
}

// ---------------- V extraction + transpose: vt[b][h][d][s] (reads fp16 kvx) ----------------
__global__ void __launch_bounds__(256)
transpose_v_kernel(const __half* __restrict__ kvxh, __half* __restrict__ vth)
{
    __shared__ __half t[32][40];
    int z = blockIdx.z;
    int b = z / NH_, h = z % NH_;
    int s0 = blockIdx.x * 32, d0 = blockIdx.y * 32;
    int tx = threadIdx.x & 31, ty = threadIdx.x >> 5;
#pragma unroll
    for (int i = ty; i < 32; i += 8)
        t[i][tx] = kvxh[((long long)(b * S_ + s0 + i)) * (NH_ * (DNOPE + DV_))
                        + h * (DNOPE + DV_) + DNOPE + d0 + tx];
    __syncthreads();
#pragma unroll
    for (int i = ty; i < 32; i += 8) {
        long long o = ((long long)z * DV_ + d0 + i) * S_ + s0 + tx;
        vth[o] = t[tx][i];
    }
}

// ---------------- launch ----------------
extern "C" void kernel_launch(void* const* d_in, const int* in_sizes, int n_in,
                              void* d_out, int out_size)
{
    const float* hs        = (const float*)d_in[0];
    const float* wq_a      = (const float*)d_in[1];
    const float* q_norm_w  = (const float*)d_in[2];
    const float* wq_b      = (const float*)d_in[3];
    const float* wkv_a     = (const float*)d_in[4];
    const float* kv_norm_w = (const float*)d_in[5];
    const float* wkv_b     = (const float*)d_in[6];
    const float* wo        = (const float*)d_in[7];
    float* out = (float*)d_out;

    cudaFuncSetAttribute(hgemm, cudaFuncAttributeMaxDynamicSharedMemorySize, GEMM_SMEM);
    cudaFuncSetAttribute(flash_attn, cudaFuncAttributeMaxDynamicSharedMemorySize, FL_SMEM);

    float *p_qa, *p_kv, *p_cos, *p_sin;
    cudaGetSymbolAddress((void**)&p_qa,  g_qa);
    cudaGetSymbolAddress((void**)&p_kv,  g_kv);
    cudaGetSymbolAddress((void**)&p_cos, g_cos);
    cudaGetSymbolAddress((void**)&p_sin, g_sin);

    __half *hs_h, *wqa_h, *wqb_h, *wkva_h, *wkvb_h, *wo_h, *qa_h, *q_h;
    __half *kvc_h, *kpe_h, *kvx_h, *vt_h, *ao_h;
    cudaGetSymbolAddress((void**)&hs_h,  g_hs_h);
    cudaGetSymbolAddress((void**)&wqa_h, g_wqa_h);
    cudaGetSymbolAddress((void**)&wqb_h, g_wqb_h);
    cudaGetSymbolAddress((void**)&wkva_h, g_wkva_h);
    cudaGetSymbolAddress((void**)&wkvb_h, g_wkvb_h);
    cudaGetSymbolAddress((void**)&wo_h,  g_wo_h);
    cudaGetSymbolAddress((void**)&qa_h,  g_qa_h);
    cudaGetSymbolAddress((void**)&q_h,   g_qh);
    cudaGetSymbolAddress((void**)&kvc_h, g_kvc_h);
    cudaGetSymbolAddress((void**)&kpe_h, g_kpe_h);
    cudaGetSymbolAddress((void**)&kvx_h, g_kvx_h);
    cudaGetSymbolAddress((void**)&vt_h,  g_vt_h);
    cudaGetSymbolAddress((void**)&ao_h,  g_ao_h);

    const float scale = 1.0f / sqrtf((float)DQK);
    auto cv8 = [](long long n) { return (int)((n / 8 + 255) / 256); };
    auto ntx_of = [](int n) { return (n + 127) / 128; };
    auto pgrid = [](int t) { return t < 296 ? t : 296; };

    freqs_kernel<<<S_, 32>>>(p_cos, p_sin);

    convert_h_kernel<<<cv8((long long)M_ * H_), 256>>>(hs, hs_h, (long long)M_ * H_);
    convert_h_kernel<<<cv8((long long)QLORA * H_), 256>>>(wq_a, wqa_h, (long long)QLORA * H_);
    convert_h_kernel<<<cv8((long long)NH_ * DQK * QLORA), 256>>>(wq_b, wqb_h, (long long)NH_ * DQK * QLORA);
    convert_h_kernel<<<cv8((long long)(KVLORA + DROPE) * H_), 256>>>(wkv_a, wkva_h, (long long)(KVLORA + DROPE) * H_);
    convert_h_kernel<<<cv8((long long)NH_ * (DNOPE + DV_) * KVLORA), 256>>>(wkv_b, wkvb_h, (long long)NH_ * (DNOPE + DV_) * KVLORA);
    convert_h_kernel<<<cv8((long long)H_ * NH_ * DV_), 256>>>(wo, wo_h, (long long)H_ * NH_ * DV_);

    // q_a = hs @ wq_a^T   [4096 x 1536] K=2048  (fp32 out)
    {
        int ntx = ntx_of(QLORA), nty = M_ / 128;
        hgemm<<<pgrid(ntx * nty), 256, GEMM_SMEM>>>(
            hs_h, wqa_h, p_qa, QLORA, H_, H_, H_, QLORA, ntx, nty, 0, nullptr, nullptr);
    }

    rmsnorm_h_kernel<<<M_, 256>>>(p_qa, QLORA, q_norm_w, qa_h, QLORA, QLORA);

    // q = q_a @ wq_b^T    [4096 x 3072] K=1536  (fp16 out + fused rope)
    {
        int ntx = ntx_of(NH_ * DQK), nty = M_ / 128;
        hgemm<<<pgrid(ntx * nty), 256, GEMM_SMEM>>>(
            qa_h, wqb_h, q_h, NH_ * DQK, QLORA, QLORA, QLORA, NH_ * DQK,
            ntx, nty, 1, p_cos, p_sin);
    }

    // kv = hs @ wkv_a^T   [4096 x 576] K=2048  (fp32 out)
    {
        int ntx = ntx_of(KVLORA + DROPE), nty = M_ / 128;
        hgemm<<<pgrid(ntx * nty), 256, GEMM_SMEM>>>(
            hs_h, wkva_h, p_kv, KVLORA + DROPE, H_, H_, H_, KVLORA + DROPE,
            ntx, nty, 0, nullptr, nullptr);
    }

    rmsnorm_h_kernel<<<M_, 256>>>(p_kv, KVLORA + DROPE, kv_norm_w, kvc_h, KVLORA, KVLORA);
    rope_k_kernel<<<M_, 32>>>(p_kv, kpe_h, p_cos, p_sin);

    // kv_x = kv_c @ wkv_b^T  [4096 x 4096] K=512  (fp16 out)
    {
        int ntx = ntx_of(NH_ * (DNOPE + DV_)), nty = M_ / 128;
        hgemm<<<pgrid(ntx * nty), 256, GEMM_SMEM>>>(
            kvc_h, wkvb_h, kvx_h, NH_ * (DNOPE + DV_), KVLORA, KVLORA, KVLORA,
            NH_ * (DNOPE + DV_), ntx, nty, 2, nullptr, nullptr);
    }

    transpose_v_kernel<<<dim3(S_ / 32, DV_ / 32, B_ * NH_), 256>>>(kvx_h, vt_h);

    // fused attention: ao_h = softmax(scale * Q K^T) V   (K from kvx_h + kpe_h)
    flash_attn<<<dim3(S_ / 128, B_ * NH_), 256, FL_SMEM>>>(
        q_h, kvx_h, kpe_h, vt_h, ao_h, scale);

    // out = ao @ wo^T   [4096 x 2048] K=2048  (fp32 out)
    {
        int ntx = ntx_of(H_), nty = M_ / 128;
        hgemm<<<pgrid(ntx * nty), 256, GEMM_SMEM>>>(
            ao_h, wo_h, out, H_, NH_ * DV_, NH_ * DV_, NH_ * DV_, H_,
            ntx, nty, 0, nullptr, nullptr);
    }
}

// round 16
// speedup vs baseline: 1.1950x; 1.0229x over previous
#include <cuda_runtime.h>
#include <cuda_fp16.h>
#include <math.h>
#include <stdint.h>

// ---------------- problem constants ----------------
#define B_    2
#define S_    2048
#define H_    2048
#define NH_   16
#define QLORA 1536
#define KVLORA 512
#define DNOPE 128
#define DROPE 64
#define DV_   128
#define DQK   192
#define M_    (B_ * S_)    // 4096
#define NQKV  (QLORA + KVLORA + DROPE)   // 2112 merged first-GEMM N

// ---------------- fp32 scratch ----------------
__device__ __align__(16) float g_qakv [(size_t)M_ * NQKV];   // merged qa|kv output
__device__ float g_cos [S_ * (DROPE / 2)];
__device__ float g_sin [S_ * (DROPE / 2)];

// ---------------- fp16 operand buffers ----------------
__device__ __align__(16) __half g_hs_h [(size_t)M_ * H_];
__device__ __align__(16) __half g_wqkva_h[(size_t)NQKV * H_];   // wq_a rows | wkv_a rows
__device__ __align__(16) __half g_wqb_h[(size_t)NH_ * DQK * QLORA];
__device__ __align__(16) __half g_wkvb_h[(size_t)NH_ * (DNOPE + DV_) * KVLORA];
__device__ __align__(16) __half g_wo_h [(size_t)H_ * NH_ * DV_];
__device__ __align__(16) __half g_qa_h [(size_t)M_ * QLORA];
__device__ __align__(16) __half g_qh   [(size_t)M_ * NH_ * DQK];
__device__ __align__(16) __half g_kvc_h[(size_t)M_ * KVLORA];
__device__ __align__(16) __half g_kpe_h[(size_t)M_ * DROPE];
__device__ __align__(16) __half g_kvx_h[(size_t)M_ * (NH_ * (DNOPE + DV_))];
__device__ __align__(16) __half g_vt_h [(size_t)B_ * NH_ * DV_ * S_];
__device__ __align__(16) __half g_ao_h [(size_t)M_ * NH_ * DV_];

// ---------------- helpers ----------------
__device__ __forceinline__ uint32_t smem_u32(const void* p) {
    uint32_t a;
    asm("{ .reg .u64 t; cvta.to.shared.u64 t, %1; cvt.u32.u64 %0, t; }" : "=r"(a) : "l"(p));
    return a;
}

__device__ __forceinline__ void cp16(uint32_t dst, const void* src, bool pred) {
    int sz = pred ? 16 : 0;
    asm volatile("cp.async.cg.shared.global [%0], [%1], 16, %2;\n"
                 :: "r"(dst), "l"(src), "r"(sz));
}
#define CP_COMMIT()   asm volatile("cp.async.commit_group;\n" ::: "memory")
#define CP_WAIT(n)    asm volatile("cp.async.wait_group %0;\n" :: "n"(n) : "memory")

__device__ __forceinline__ void mma_fp16(float* c, const uint32_t* a, const uint32_t* b) {
    asm volatile(
        "mma.sync.aligned.m16n8k16.row.col.f32.f16.f16.f32 "
        "{%0,%1,%2,%3}, {%4,%5,%6,%7}, {%8,%9}, {%0,%1,%2,%3};\n"
        : "+f"(c[0]), "+f"(c[1]), "+f"(c[2]), "+f"(c[3])
        : "r"(a[0]), "r"(a[1]), "r"(a[2]), "r"(a[3]), "r"(b[0]), "r"(b[1]));
}

__device__ __forceinline__ void ldsm_x4(uint32_t* r, uint32_t addr) {
    asm volatile("ldmatrix.sync.aligned.m8n8.x4.shared.b16 {%0,%1,%2,%3}, [%4];"
        : "=r"(r[0]), "=r"(r[1]), "=r"(r[2]), "=r"(r[3]) : "r"(addr));
}

__device__ __forceinline__ uint32_t pack_h2(float a, float b) {
    __half2 h = __floats2half2_rn(a, b);
    return *(uint32_t*)&h;
}

// ---------------- persistent pipelined fp16 tensor-core GEMM, tile 128x128 ----------------
// C[m,n] = sum_k A[m,k] * B[n,k]   (B row-major [n][k], K-contiguous)
// 256 threads, K-chunk 32, 4-stage cp.async, 2 CTA/SM. Grid = min(tiles, 296).
// mode 0: fp32 C.  mode 1: fp16 C + fused RoPE on d>=128 (q path).  mode 2: fp16 C.
// Requires K >= 128 (nk >= 4) — true at all call sites.
#define STG_A   0
#define STG_B   10240
#define STG_BYTES 20480
#define GEMM_SMEM (4 * STG_BYTES)

extern __shared__ char sm_raw[];

__global__ void __launch_bounds__(256, 2)
hgemm(const __half* __restrict__ A,
      const __half* __restrict__ B,
      void* __restrict__ Cv,
      int N, int K, int lda, int ldb, int ldc,
      int ntx, int nty, int mode,
      const float* __restrict__ cosd, const float* __restrict__ sind)
{
    const int tid = threadIdx.x;
    const int lane = tid & 31, w = tid >> 5;
    const int wm = (w >> 1) * 32, wn = (w & 1) * 64;
    const int fr = lane >> 2, fc = (lane & 3) * 2;
    const int nk = K >> 5;

    const uint32_t smem = smem_u32(sm_raw);

    uint32_t aoff[2], boff[4];
    {
        int r = wm + (lane & 15);
        int c = (lane >> 4) * 8;
        aoff[0] = (uint32_t)((r * 40 + c) * 2);
        aoff[1] = (uint32_t)(((r + 16) * 40 + c) * 2);
        int lnB = lane & 7;
        int pHi = lane >> 4;
        int kh  = ((lane >> 3) & 1) * 8;
#pragma unroll
        for (int p = 0; p < 4; p++) {
            int n = wn + (2 * p + pHi) * 8 + lnB;
            boff[p] = (uint32_t)((n * 40 + kh) * 2);
        }
    }

    const int lrow0 = tid >> 2, lch = tid & 3;
    const uint32_t so1 = (uint32_t)(lrow0 * 80 + lch * 16);
    const uint32_t so2 = (uint32_t)((lrow0 + 64) * 80 + lch * 16);
    const int ntiles = ntx * nty;

    for (int tile = blockIdx.x; tile < ntiles; tile += gridDim.x) {
        const int m0 = (tile / ntx) * 128;
        const int n0 = (tile % ntx) * 128;

        const __half* gA  = A + (long long)(m0 + lrow0) * lda + lch * 8;
        const __half* gA2 = gA + 64ll * lda;
        const bool bp1 = (n0 + lrow0) < N;
        const bool bp2 = (n0 + lrow0 + 64) < N;
        const __half* gB  = B + (long long)(n0 + (bp1 ? lrow0 : 0)) * ldb + lch * 8;
        const __half* gB2 = B + (long long)(n0 + (bp2 ? lrow0 + 64 : 0)) * ldb + lch * 8;

        auto load_stage = [&](int kc, int st) {
            uint32_t sb = smem + st * STG_BYTES;
            cp16(sb + STG_A + so1, gA  + kc, true);
            cp16(sb + STG_A + so2, gA2 + kc, true);
            cp16(sb + STG_B + so1, gB  + kc, bp1);
            cp16(sb + STG_B + so2, gB2 + kc, bp2);
            CP_COMMIT();
        };

        float acc[2][8][4] = {};

        load_stage(0, 0);
        load_stage(32, 1);
        load_stage(64, 2);

        for (int k = 0; k < nk; k++) {
            const int st = k & 3;
            if (k + 3 < nk) load_stage((k + 3) * 32, (k + 3) & 3);
            else CP_COMMIT();
            CP_WAIT(3);
            __syncthreads();

            const uint32_t sb = smem + st * STG_BYTES;

#pragma unroll
            for (int ks = 0; ks < 2; ks++) {
                const uint32_t kB = ks * 32;
                uint32_t a[2][4];
#pragma unroll
                for (int mt = 0; mt < 2; mt++)
                    ldsm_x4(a[mt], sb + STG_A + aoff[mt] + kB);
#pragma unroll
                for (int p = 0; p < 4; p++) {
                    uint32_t bh[4];
                    ldsm_x4(bh, sb + STG_B + boff[p] + kB);
#pragma unroll
                    for (int sub = 0; sub < 2; sub++) {
                        const int nt = 2 * p + sub;
#pragma unroll
                        for (int mt = 0; mt < 2; mt++)
                            mma_fp16(acc[mt][nt], a[mt], bh + 2 * sub);
                    }
                }
            }
            __syncthreads();
        }

        // ---- epilogue ----
        if (mode == 0) {
            float* C = (float*)Cv;
#pragma unroll
            for (int mt = 0; mt < 2; mt++) {
                int row = m0 + wm + mt * 16 + fr;
#pragma unroll
                for (int nt = 0; nt < 8; nt++) {
                    int col = n0 + wn + nt * 8 + fc;
                    if (col < N) {
                        C[(long long)row * ldc + col]           = acc[mt][nt][0];
                        C[(long long)row * ldc + col + 1]       = acc[mt][nt][1];
                        C[(long long)(row + 8) * ldc + col]     = acc[mt][nt][2];
                        C[(long long)(row + 8) * ldc + col + 1] = acc[mt][nt][3];
                    }
                }
            }
        } else {
            __half* C = (__half*)Cv;
#pragma unroll
            for (int mt = 0; mt < 2; mt++) {
                int row = m0 + wm + mt * 16 + fr;
#pragma unroll
                for (int nt = 0; nt < 8; nt++) {
                    int col = n0 + wn + nt * 8 + fc;
                    if (col >= N) continue;
                    float c0 = acc[mt][nt][0], c1 = acc[mt][nt][1];
                    float c2 = acc[mt][nt][2], c3 = acc[mt][nt][3];
                    if (mode == 1) {
                        int d = col % DQK;
                        if (d >= DNOPE) {
                            int i = (d - DNOPE) >> 1;
                            int t0 = row & (S_ - 1), t1 = (row + 8) & (S_ - 1);
                            float cs0 = cosd[t0 * 32 + i], sn0 = sind[t0 * 32 + i];
                            float cs1 = cosd[t1 * 32 + i], sn1 = sind[t1 * 32 + i];
                            float r0 = c0 * cs0 - c1 * sn0, i0 = c0 * sn0 + c1 * cs0;
                            float r1 = c2 * cs1 - c3 * sn1, i1 = c2 * sn1 + c3 * cs1;
                            c0 = r0; c1 = i0; c2 = r1; c3 = i1;
                        }
                    }
                    *(__half2*)(C + (long long)row * ldc + col) = __floats2half2_rn(c0, c1);
                    *(__half2*)(C + (long long)(row + 8) * ldc + col) = __floats2half2_rn(c2, c3);
                }
            }
        }
    }
}

// ---------------- fused flash attention (unchanged) ----------------
#define FL_Q    0
#define FL_K    51200
#define FL_KS   25600
#define FL_V    102400
#define FL_P    120832
#define FL_RED  139264
#define FL_SMEM 141312

__global__ void __launch_bounds__(256, 1)
flash_attn(const __half* __restrict__ Qg,
           const __half* __restrict__ Kvx,
           const __half* __restrict__ Kpe,
           const __half* __restrict__ Vh,
           __half* __restrict__ Oh, float scale)
{
    const int z  = blockIdx.y;
    const int bb = z >> 4, hh = z & 15;
    const int q0 = blockIdx.x * 128;
    const int tid = threadIdx.x, lane = tid & 31, w = tid >> 5;
    const int wq = w >> 1, wk = w & 1;
    const int fr = lane >> 2, fc = (lane & 3) * 2;

    const uint32_t smem = smem_u32(sm_raw);

    const __half* Qb  = Qg + (long long)bb * S_ * (NH_ * DQK) + hh * DQK;
    const __half* Kvb = Kvx + (long long)bb * S_ * (NH_ * (DNOPE + DV_)) + hh * (DNOPE + DV_);
    const __half* Kpb = Kpe + (long long)bb * S_ * DROPE;
    const __half* Vhb = Vh + (long long)z * DV_ * S_;

    auto load_Q = [&]() {
#pragma unroll
        for (int j = 0; j < 12; j++) {
            int idx = tid + 256 * j;
            int r = idx / 24, ch = idx % 24;
            cp16(smem + FL_Q + (uint32_t)(r * 200 + ch * 8) * 2,
                 Qb + (long long)(q0 + r) * (NH_ * DQK) + ch * 8, true);
        }
    };
    auto load_K = [&](int kb, int st) {
        uint32_t base = smem + FL_K + st * FL_KS;
#pragma unroll
        for (int j = 0; j < 6; j++) {
            int idx = tid + 256 * j;
            int r = idx / 24, ch = idx % 24;
            uint32_t so = (uint32_t)(r * 200 + ch * 8) * 2;
            if (ch < 16)
                cp16(base + so, Kvb + (long long)(kb * 64 + r) * (NH_ * (DNOPE + DV_)) + ch * 8, true);
            else
                cp16(base + so, Kpb + (long long)(kb * 64 + r) * DROPE + (ch - 16) * 8, true);
        }
    };
    auto load_V = [&](int kb) {
#pragma unroll
        for (int j = 0; j < 4; j++) {
            int idx = tid + 256 * j;
            int d = idx >> 3, ch = idx & 7;
            cp16(smem + FL_V + (uint32_t)(d * 72 + ch * 8) * 2,
                 Vhb + (long long)d * S_ + kb * 64 + ch * 8, true);
        }
    };

    uint32_t aQ[2], aP[2], bK[2], bV[4];
    {
        int r = wq * 32 + (lane & 15);
        int c = (lane >> 4) * 8;
        aQ[0] = (uint32_t)((r * 200 + c) * 2);
        aQ[1] = (uint32_t)(((r + 16) * 200 + c) * 2);
        aP[0] = (uint32_t)((r * 72 + c) * 2);
        aP[1] = (uint32_t)(((r + 16) * 72 + c) * 2);
        int lnB = lane & 7, pHi = lane >> 4, kh = ((lane >> 3) & 1) * 8;
#pragma unroll
        for (int p = 0; p < 2; p++) {
            int n = wk * 32 + (2 * p + pHi) * 8 + lnB;
            bK[p] = (uint32_t)((n * 200 + kh) * 2);
        }
#pragma unroll
        for (int p = 0; p < 4; p++) {
            int n = wk * 64 + (2 * p + pHi) * 8 + lnB;
            bV[p] = (uint32_t)((n * 72 + kh) * 2);
        }
    }

    float acc_o[2][8][4] = {};
    float m_st[4], l_st[4];
#pragma unroll
    for (int i = 0; i < 4; i++) { m_st[i] = -1e30f; l_st[i] = 0.f; }

    float* redm = (float*)(sm_raw + FL_RED);
    float* reds = (float*)(sm_raw + FL_RED + 1024);
    int rowi[4];
#pragma unroll
    for (int mt = 0; mt < 2; mt++)
#pragma unroll
        for (int rr = 0; rr < 2; rr++)
            rowi[mt * 2 + rr] = wq * 32 + mt * 16 + rr * 8 + fr;

    load_Q(); load_K(0, 0); CP_COMMIT();
    load_V(0);              CP_COMMIT();
    load_K(1, 1);           CP_COMMIT();

    for (int kb = 0; kb < 32; kb++) {
        if (kb == 31) { CP_WAIT(1); } else { CP_WAIT(2); }
        __syncthreads();

        float acc_s[2][4][4] = {};
        const uint32_t kbase = smem + FL_K + (kb & 1) * FL_KS;
#pragma unroll
        for (int ks = 0; ks < 12; ks++) {
            const uint32_t kB = ks * 32;
            uint32_t a[2][4];
            ldsm_x4(a[0], smem + FL_Q + aQ[0] + kB);
            ldsm_x4(a[1], smem + FL_Q + aQ[1] + kB);
#pragma unroll
            for (int p = 0; p < 2; p++) {
                uint32_t bh[4];
                ldsm_x4(bh, kbase + bK[p] + kB);
#pragma unroll
                for (int sub = 0; sub < 2; sub++) {
                    const int nt = 2 * p + sub;
#pragma unroll
                    for (int mt = 0; mt < 2; mt++)
                        mma_fp16(acc_s[mt][nt], a[mt], bh + 2 * sub);
                }
            }
        }
#pragma unroll
        for (int mt = 0; mt < 2; mt++)
#pragma unroll
            for (int nt = 0; nt < 4; nt++)
#pragma unroll
                for (int c = 0; c < 4; c++) acc_s[mt][nt][c] *= scale;

#pragma unroll
        for (int sl = 0; sl < 4; sl++) {
            int mt = sl >> 1, rr = sl & 1;
            float v = -1e30f;
#pragma unroll
            for (int nt = 0; nt < 4; nt++) {
                v = fmaxf(v, acc_s[mt][nt][2 * rr]);
                v = fmaxf(v, acc_s[mt][nt][2 * rr + 1]);
            }
            v = fmaxf(v, __shfl_xor_sync(0xffffffffu, v, 1));
            v = fmaxf(v, __shfl_xor_sync(0xffffffffu, v, 2));
            if ((lane & 3) == 0) redm[wk * 128 + rowi[sl]] = v;
        }
        __syncthreads();

        float alpha[4];
#pragma unroll
        for (int sl = 0; sl < 4; sl++) {
            float bm = fmaxf(redm[rowi[sl]], redm[128 + rowi[sl]]);
            float mn = fmaxf(m_st[sl], bm);
            alpha[sl] = __expf(m_st[sl] - mn);
            m_st[sl] = mn;
        }

#pragma unroll
        for (int sl = 0; sl < 4; sl++) {
            int mt = sl >> 1, rr = sl & 1;
            int prow = rowi[sl];
            float s = 0.f;
#pragma unroll
            for (int nt = 0; nt < 4; nt++) {
                float p0 = __expf(acc_s[mt][nt][2 * rr]     - m_st[sl]);
                float p1 = __expf(acc_s[mt][nt][2 * rr + 1] - m_st[sl]);
                s += p0 + p1;
                *(__half2*)(sm_raw + FL_P + (prow * 72 + wk * 32 + nt * 8 + fc) * 2)
                    = __floats2half2_rn(p0, p1);
            }
            s += __shfl_xor_sync(0xffffffffu, s, 1);
            s += __shfl_xor_sync(0xffffffffu, s, 2);
            if ((lane & 3) == 0) reds[wk * 128 + prow] = s;
        }

        if (kb == 31) { CP_WAIT(0); } else { CP_WAIT(1); }
        __syncthreads();

#pragma unroll
        for (int sl = 0; sl < 4; sl++)
            l_st[sl] = alpha[sl] * l_st[sl] + reds[rowi[sl]] + reds[128 + rowi[sl]];

#pragma unroll
        for (int mt = 0; mt < 2; mt++)
#pragma unroll
            for (int nt = 0; nt < 8; nt++)
#pragma unroll
                for (int rr = 0; rr < 2; rr++) {
                    float a = alpha[mt * 2 + rr];
                    acc_o[mt][nt][2 * rr]     *= a;
                    acc_o[mt][nt][2 * rr + 1] *= a;
                }

#pragma unroll
        for (int ks = 0; ks < 4; ks++) {
            const uint32_t kB = ks * 32;
            uint32_t a[2][4];
            ldsm_x4(a[0], smem + FL_P + aP[0] + kB);
            ldsm_x4(a[1], smem + FL_P + aP[1] + kB);
#pragma unroll
            for (int p = 0; p < 4; p++) {
                uint32_t bh[4];
                ldsm_x4(bh, smem + FL_V + bV[p] + kB);
#pragma unroll
                for (int sub = 0; sub < 2; sub++) {
                    const int nt = 2 * p + sub;
#pragma unroll
                    for (int mt = 0; mt < 2; mt++)
                        mma_fp16(acc_o[mt][nt], a[mt], bh + 2 * sub);
                }
            }
        }
        __syncthreads();

        if (kb + 1 < 32) { load_V(kb + 1);         CP_COMMIT(); }
        if (kb + 2 < 32) { load_K(kb + 2, kb & 1); CP_COMMIT(); }
    }

    __half* Ob = Oh + (long long)bb * S_ * (NH_ * DV_) + hh * DV_;
#pragma unroll
    for (int mt = 0; mt < 2; mt++)
#pragma unroll
        for (int rr = 0; rr < 2; rr++) {
            int sl = mt * 2 + rr;
            float inv = 1.f / l_st[sl];
            long long row = q0 + rowi[sl];
#pragma unroll
            for (int nt = 0; nt < 8; nt++) {
                int col = wk * 64 + nt * 8 + fc;
                *(__half2*)(Ob + row * (NH_ * DV_) + col) =
                    __floats2half2_rn(acc_o[mt][nt][2 * rr] * inv,
                                      acc_o[mt][nt][2 * rr + 1] * inv);
            }
        }
}

// ---------------- fp32 -> fp16, vectorized 8 elems/thread ----------------
__global__ void convert_h_kernel(const float* __restrict__ x,
                                 __half* __restrict__ h, long long n)
{
    long long i = ((long long)blockIdx.x * 256 + threadIdx.x) * 8;
    if (i < n) {
        float4 a = *(const float4*)(x + i);
        float4 b = *(const float4*)(x + i + 4);
        uint4 o;
        o.x = pack_h2(a.x, a.y);
        o.y = pack_h2(a.z, a.w);
        o.z = pack_h2(b.x, b.y);
        o.w = pack_h2(b.z, b.w);
        *(uint4*)(h + i) = o;
    }
}

// ---------------- RMSNorm -> fp16, vectorized ----------------
__global__ void __launch_bounds__(256)
rmsnorm_h_kernel(const float* __restrict__ x, int ldx, const float* __restrict__ w,
                 __half* __restrict__ yh, int ldy, int cols)
{
    const int row = blockIdx.x;
    const float* xr = x + (long long)row * ldx;
    float ss = 0.f;
    for (int c = threadIdx.x * 4; c < cols; c += 1024) {
        float4 v = *(const float4*)(xr + c);
        ss += v.x * v.x + v.y * v.y + v.z * v.z + v.w * v.w;
    }
    __shared__ float red[256];
    red[threadIdx.x] = ss;
    __syncthreads();
    for (int s = 128; s > 0; s >>= 1) {
        if (threadIdx.x < s) red[threadIdx.x] += red[threadIdx.x + s];
        __syncthreads();
    }
    float inv = 1.f / sqrtf(red[0] / (float)cols + 1e-6f);
    long long base = (long long)row * ldy;
    for (int c = threadIdx.x * 4; c < cols; c += 1024) {
        float4 v = *(const float4*)(xr + c);
        float4 wv = *(const float4*)(w + c);
        uint2 o;
        o.x = pack_h2(wv.x * v.x * inv, wv.y * v.y * inv);
        o.y = pack_h2(wv.z * v.z * inv, wv.w * v.w * inv);
        *(uint2*)(yh + base + c) = o;
    }
}

// ---------------- RoPE ----------------
__global__ void freqs_kernel(float* __restrict__ cosd, float* __restrict__ sind)
{
    int t = blockIdx.x, i = threadIdx.x;
    double inv = pow(10000.0, -(double)(2 * i) / (double)DROPE);
    double f = (double)t * inv;
    cosd[t * 32 + i] = (float)cos(f);
    sind[t * 32 + i] = (float)sin(f);
}

// rope on k_pe (reads fp32 at kv + m*ld, 64 floats) -> fp16
__global__ void rope_k_kernel(const float* __restrict__ kv, int ld,
                              __half* __restrict__ kpeh,
                              const float* __restrict__ cosd, const float* __restrict__ sind)
{
    int m = blockIdx.x;
    int t = m & (S_ - 1);
    int i = threadIdx.x;
    float cs = cosd[t * 32 + i], sn = sind[t * 32 + i];
    long long base = (long long)m * ld + 2 * i;
    float e = kv[base], o = kv[base + 1];
    *(__half2*)(kpeh + (long long)m * DROPE + 2 * i) =
        __floats2half2_rn(e * cs - o * sn, e * sn + o * cs);
}

// ---------------- V extraction + transpose: vt[b][h][d][s] (reads fp16 kvx) ----------------
__global__ void __launch_bounds__(256)
transpose_v_kernel(const __half* __restrict__ kvxh, __half* __restrict__ vth)
{
    __shared__ __half t[32][40];
    int z = blockIdx.z;
    int b = z / NH_, h = z % NH_;
    int s0 = blockIdx.x * 32, d0 = blockIdx.y * 32;
    int tx = threadIdx.x & 31, ty = threadIdx.x >> 5;
#pragma unroll
    for (int i = ty; i < 32; i += 8)
        t[i][tx] = kvxh[((long long)(b * S_ + s0 + i)) * (NH_ * (DNOPE + DV_))
                        + h * (DNOPE + DV_) + DNOPE + d0 + tx];
    __syncthreads();
#pragma unroll
    for (int i = ty; i < 32; i += 8) {
        long long o = ((long long)z * DV_ + d0 + i) * S_ + s0 + tx;
        vth[o] = t[tx][i];
    }
}

// ---------------- launch ----------------
extern "C" void kernel_launch(void* const* d_in, const int* in_sizes, int n_in,
                              void* d_out, int out_size)
{
    const float* hs        = (const float*)d_in[0];
    const float* wq_a      = (const float*)d_in[1];
    const float* q_norm_w  = (const float*)d_in[2];
    const float* wq_b      = (const float*)d_in[3];
    const float* wkv_a     = (const float*)d_in[4];
    const float* kv_norm_w = (const float*)d_in[5];
    const float* wkv_b     = (const float*)d_in[6];
    const float* wo        = (const float*)d_in[7];
    float* out = (float*)d_out;

    cudaFuncSetAttribute(hgemm, cudaFuncAttributeMaxDynamicSharedMemorySize, GEMM_SMEM);
    cudaFuncSetAttribute(flash_attn, cudaFuncAttributeMaxDynamicSharedMemorySize, FL_SMEM);

    float *p_qakv, *p_cos, *p_sin;
    cudaGetSymbolAddress((void**)&p_qakv, g_qakv);
    cudaGetSymbolAddress((void**)&p_cos, g_cos);
    cudaGetSymbolAddress((void**)&p_sin, g_sin);

    __half *hs_h, *wqkva_h, *wqb_h, *wkvb_h, *wo_h, *qa_h, *q_h;
    __half *kvc_h, *kpe_h, *kvx_h, *vt_h, *ao_h;
    cudaGetSymbolAddress((void**)&hs_h,  g_hs_h);
    cudaGetSymbolAddress((void**)&wqkva_h, g_wqkva_h);
    cudaGetSymbolAddress((void**)&wqb_h, g_wqb_h);
    cudaGetSymbolAddress((void**)&wkvb_h, g_wkvb_h);
    cudaGetSymbolAddress((void**)&wo_h,  g_wo_h);
    cudaGetSymbolAddress((void**)&qa_h,  g_qa_h);
    cudaGetSymbolAddress((void**)&q_h,   g_qh);
    cudaGetSymbolAddress((void**)&kvc_h, g_kvc_h);
    cudaGetSymbolAddress((void**)&kpe_h, g_kpe_h);
    cudaGetSymbolAddress((void**)&kvx_h, g_kvx_h);
    cudaGetSymbolAddress((void**)&vt_h,  g_vt_h);
    cudaGetSymbolAddress((void**)&ao_h,  g_ao_h);

    const float scale = 1.0f / sqrtf((float)DQK);
    auto cv8 = [](long long n) { return (int)((n / 8 + 255) / 256); };
    auto ntx_of = [](int n) { return (n + 127) / 128; };
    auto pgrid = [](int t) { return t < 296 ? t : 296; };

    freqs_kernel<<<S_, 32>>>(p_cos, p_sin);

    convert_h_kernel<<<cv8((long long)M_ * H_), 256>>>(hs, hs_h, (long long)M_ * H_);
    // merged first-GEMM weights: wq_a rows then wkv_a rows
    convert_h_kernel<<<cv8((long long)QLORA * H_), 256>>>(wq_a, wqkva_h, (long long)QLORA * H_);
    convert_h_kernel<<<cv8((long long)(KVLORA + DROPE) * H_), 256>>>(
        wkv_a, wqkva_h + (size_t)QLORA * H_, (long long)(KVLORA + DROPE) * H_);
    convert_h_kernel<<<cv8((long long)NH_ * DQK * QLORA), 256>>>(wq_b, wqb_h, (long long)NH_ * DQK * QLORA);
    convert_h_kernel<<<cv8((long long)NH_ * (DNOPE + DV_) * KVLORA), 256>>>(wkv_b, wkvb_h, (long long)NH_ * (DNOPE + DV_) * KVLORA);
    convert_h_kernel<<<cv8((long long)H_ * NH_ * DV_), 256>>>(wo, wo_h, (long long)H_ * NH_ * DV_);

    // merged: qakv = hs @ [wq_a; wkv_a]^T   [4096 x 2112] K=2048  (fp32 out)
    {
        int ntx = ntx_of(NQKV), nty = M_ / 128;   // 17 x 32 = 544 tiles
        hgemm<<<pgrid(ntx * nty), 256, GEMM_SMEM>>>(
            hs_h, wqkva_h, p_qakv, NQKV, H_, H_, H_, NQKV, ntx, nty, 0, nullptr, nullptr);
    }

    // rmsnorm over qa part (cols 0..1535)
    rmsnorm_h_kernel<<<M_, 256>>>(p_qakv, NQKV, q_norm_w, qa_h, QLORA, QLORA);
    // rmsnorm over kv_c part (cols 1536..2047)
    rmsnorm_h_kernel<<<M_, 256>>>(p_qakv + QLORA, NQKV, kv_norm_w, kvc_h, KVLORA, KVLORA);
    // rope k_pe (cols 2048..2111)
    rope_k_kernel<<<M_, 32>>>(p_qakv + QLORA + KVLORA, NQKV, kpe_h, p_cos, p_sin);

    // q = q_a @ wq_b^T    [4096 x 3072] K=1536  (fp16 out + fused rope)
    {
        int ntx = ntx_of(NH_ * DQK), nty = M_ / 128;
        hgemm<<<pgrid(ntx * nty), 256, GEMM_SMEM>>>(
            qa_h, wqb_h, q_h, NH_ * DQK, QLORA, QLORA, QLORA, NH_ * DQK,
            ntx, nty, 1, p_cos, p_sin);
    }

    // kv_x = kv_c @ wkv_b^T  [4096 x 4096] K=512  (fp16 out)
    {
        int ntx = ntx_of(NH_ * (DNOPE + DV_)), nty = M_ / 128;
        hgemm<<<pgrid(ntx * nty), 256, GEMM_SMEM>>>(
            kvc_h, wkvb_h, kvx_h, NH_ * (DNOPE + DV_), KVLORA, KVLORA, KVLORA,
            NH_ * (DNOPE + DV_), ntx, nty, 2, nullptr, nullptr);
    }

    transpose_v_kernel<<<dim3(S_ / 32, DV_ / 32, B_ * NH_), 256>>>(kvx_h, vt_h);

    // fused attention: ao_h = softmax(scale * Q K^T) V
    flash_attn<<<dim3(S_ / 128, B_ * NH_), 256, FL_SMEM>>>(
        q_h, kvx_h, kpe_h, vt_h, ao_h, scale);

    // out = ao @ wo^T   [4096 x 2048] K=2048  (fp32 out)
    {
        int ntx = ntx_of(H_), nty = M_ / 128;
        hgemm<<<pgrid(ntx * nty), 256, GEMM_SMEM>>>(
            ao_h, wo_h, out, H_, NH_ * DV_, NH_ * DV_, NH_ * DV_, H_,
            ntx, nty, 0, nullptr, nullptr);
    }
}